// round 1
// baseline (speedup 1.0000x reference)
#include <cuda_runtime.h>
#include <cuda_bf16.h>
#include <math.h>

// Problem constants
#define BB 2
#define SS 2048
#define TT 2048
#define DIN 2048
#define DOUT 2048
#define HH 16
#define RD 64
#define HALF_RD 32
#define LL 512
#define HD 128
#define ROWS (BB*SS)          // 4096

// ---------------- device scratch (static; no allocations in kernel_launch) ----
__device__ float g_ckv  [BB*SS*LL];          // [b,s,l]            8 MB
__device__ float g_krope[BB*SS*HH*RD];       // row=b*S+s, col=h*64+r (ld 1024) 16 MB
__device__ float g_q    [BB*SS*(DOUT+HH*RD)];// [row, 3072]        48 MB
__device__ float g_qabs [ROWS*HH*LL];        // row=b*S+s, col=h*512+l (ld 8192) 128 MB
__device__ float g_scores[(long)BB*HH*SS*TT];// [(b*16+h), s, t]   512 MB
__device__ float g_ctxlat[ROWS*HH*LL];       // row, col=h*512+l (ld 8192) 128 MB
__device__ float g_ctx  [ROWS*DOUT];         // [row, 2048]        32 MB

// ---------------- generic tiled GEMM ------------------------------------------
// C = A @ B(^T)   (optionally +=)
// A: [M,K], lda (row-major, K contiguous)
// transB=1: B: [N,K], ldb (K contiguous)  -> C[m,n] = sum_k A[m,k]*B[n,k]
// transB=0: B: [K,N], ldb (N contiguous)  -> C[m,n] = sum_k A[m,k]*B[k,n]
// Batched over blockIdx.z: zo=z/zInner, zi=z%zInner, per-operand strides.
// REQUIREMENTS (guaranteed by caller): M%128==0, N%128==0, K%8==0,
// lda/ldb %4==0, base offsets %4==0.
#define BM 128
#define BN 128
#define BK 8
#define TM 8
#define TN 8

__global__ void __launch_bounds__(256)
gemm_kernel(const float* __restrict__ Ab, const float* __restrict__ Bb,
            float* __restrict__ Cb,
            int M, int N, int K, int lda, int ldb, int ldc,
            int zInner, long sAo, long sAi, long sBo, long sBi,
            long sCo, long sCi, int transB, int accumulate)
{
    int z  = blockIdx.z;
    int zo = z / zInner, zi = z % zInner;
    const float* A = Ab + zo * sAo + zi * sAi;
    const float* B = Bb + zo * sBo + zi * sBi;
    float*       C = Cb + zo * sCo + zi * sCi;

    __shared__ float As[BK][BM];
    __shared__ float Bs[BK][BN];

    const int m0  = blockIdx.y * BM;
    const int n0  = blockIdx.x * BN;
    const int tid = threadIdx.x;
    const int tx  = tid % 16;
    const int ty  = tid / 16;

    float acc[TM][TN];
    #pragma unroll
    for (int i = 0; i < TM; i++)
        #pragma unroll
        for (int j = 0; j < TN; j++) acc[i][j] = 0.0f;

    const int arow = tid >> 1;          // 0..127
    const int acol = (tid & 1) * 4;     // 0 or 4
    const int brow_n = tid >> 5;        // 0..7   (nn)
    const int bcol_n = (tid & 31) * 4;  // 0..124 (nn)

    for (int k0 = 0; k0 < K; k0 += BK) {
        float4 av = *(const float4*)(A + (long)(m0 + arow) * lda + k0 + acol);
        As[acol + 0][arow] = av.x;
        As[acol + 1][arow] = av.y;
        As[acol + 2][arow] = av.z;
        As[acol + 3][arow] = av.w;

        if (transB) {
            float4 bv = *(const float4*)(B + (long)(n0 + arow) * ldb + k0 + acol);
            Bs[acol + 0][arow] = bv.x;
            Bs[acol + 1][arow] = bv.y;
            Bs[acol + 2][arow] = bv.z;
            Bs[acol + 3][arow] = bv.w;
        } else {
            float4 bv = *(const float4*)(B + (long)(k0 + brow_n) * ldb + n0 + bcol_n);
            *(float4*)&Bs[brow_n][bcol_n] = bv;
        }
        __syncthreads();

        #pragma unroll
        for (int kk = 0; kk < BK; kk++) {
            float ra[TM], rb[TN];
            #pragma unroll
            for (int i = 0; i < TM; i++) ra[i] = As[kk][ty * TM + i];
            #pragma unroll
            for (int j = 0; j < TN; j++) rb[j] = Bs[kk][tx * TN + j];
            #pragma unroll
            for (int i = 0; i < TM; i++)
                #pragma unroll
                for (int j = 0; j < TN; j++)
                    acc[i][j] += ra[i] * rb[j];
        }
        __syncthreads();
    }

    #pragma unroll
    for (int i = 0; i < TM; i++) {
        long crow = (long)(m0 + ty * TM + i) * ldc + n0 + tx * TN;
        #pragma unroll
        for (int j = 0; j < TN; j++) {
            if (accumulate) C[crow + j] += acc[i][j];
            else            C[crow + j]  = acc[i][j];
        }
    }
}

// ---------------- RMSNorm over rows of length L=512 ---------------------------
__global__ void rmsnorm_kernel(float* __restrict__ data,
                               const float* __restrict__ w)
{
    const int row = blockIdx.x;
    float* p = data + (long)row * LL;
    float ss = 0.0f;
    for (int i = threadIdx.x; i < LL; i += blockDim.x) {
        float v = p[i];
        ss += v * v;
    }
    __shared__ float red[32];
    for (int o = 16; o; o >>= 1) ss += __shfl_xor_sync(0xffffffffu, ss, o);
    if ((threadIdx.x & 31) == 0) red[threadIdx.x >> 5] = ss;
    __syncthreads();
    if (threadIdx.x < 32) {
        float v = (threadIdx.x < (blockDim.x >> 5)) ? red[threadIdx.x] : 0.0f;
        for (int o = 16; o; o >>= 1) v += __shfl_xor_sync(0xffffffffu, v, o);
        if (threadIdx.x == 0) red[0] = v;
    }
    __syncthreads();
    float ms   = red[0] / (float)LL;
    float rstd = rsqrtf(ms + 1e-6f);
    for (int i = threadIdx.x; i < LL; i += blockDim.x)
        p[i] = p[i] * rstd * w[i];
}

// ---------------- RoPE (GPT-NeoX style), in place ------------------------------
// data rows = b*S+s (4096), each row has H heads of RD at col = colbase + h*RD.
__global__ void rope_kernel(float* __restrict__ data, int ld, int colbase,
                            const int* __restrict__ offset_p)
{
    long idx = (long)blockIdx.x * blockDim.x + threadIdx.x;
    const long total = (long)ROWS * HH * HALF_RD;
    if (idx >= total) return;
    int  j   = (int)(idx % HALF_RD);
    int  h   = (int)((idx / HALF_RD) % HH);
    long row = idx / (HALF_RD * HH);
    int  s   = (int)(row % SS);
    float pos = (float)(s + *offset_p);
    // inv_freq[j] = 10000^{-j/32}
    float inv = expf(-(float)j * (logf(10000.0f) / 32.0f));
    float ang = pos * inv;
    float c, si;
    __sincosf(ang, &si, &c);
    // use accurate versions to match fp32 reference closely
    c  = cosf(ang);
    si = sinf(ang);
    float* p = data + row * (long)ld + colbase + h * RD;
    float x1 = p[j];
    float x2 = p[j + HALF_RD];
    p[j]           = x1 * c - x2 * si;
    p[j + HALF_RD] = x2 * c + x1 * si;
}

// ---------------- masked scaled softmax over score rows -----------------------
__global__ void softmax_kernel(float* __restrict__ scores,
                               const int* __restrict__ offset_p)
{
    const long row = blockIdx.x;            // (b*H+h)*S + s
    const int  s   = (int)(row % SS);
    int valid = s + *offset_p + 1;
    if (valid > TT) valid = TT;
    float* p = scores + row * (long)TT;
    const float scale = rsqrtf((float)(HD + RD));

    float m = -INFINITY;
    for (int t = threadIdx.x; t < valid; t += blockDim.x)
        m = fmaxf(m, p[t] * scale);

    __shared__ float red[32];
    for (int o = 16; o; o >>= 1) m = fmaxf(m, __shfl_xor_sync(0xffffffffu, m, o));
    if ((threadIdx.x & 31) == 0) red[threadIdx.x >> 5] = m;
    __syncthreads();
    if (threadIdx.x < 32) {
        float v = (threadIdx.x < (blockDim.x >> 5)) ? red[threadIdx.x] : -INFINITY;
        for (int o = 16; o; o >>= 1) v = fmaxf(v, __shfl_xor_sync(0xffffffffu, v, o));
        if (threadIdx.x == 0) red[0] = v;
    }
    __syncthreads();
    m = red[0];
    __syncthreads();

    float sum = 0.0f;
    for (int t = threadIdx.x; t < valid; t += blockDim.x) {
        float e = expf(p[t] * scale - m);
        p[t] = e;
        sum += e;
    }
    for (int o = 16; o; o >>= 1) sum += __shfl_xor_sync(0xffffffffu, sum, o);
    if ((threadIdx.x & 31) == 0) red[threadIdx.x >> 5] = sum;
    __syncthreads();
    if (threadIdx.x < 32) {
        float v = (threadIdx.x < (blockDim.x >> 5)) ? red[threadIdx.x] : 0.0f;
        for (int o = 16; o; o >>= 1) v += __shfl_xor_sync(0xffffffffu, v, o);
        if (threadIdx.x == 0) red[0] = v;
    }
    __syncthreads();
    float inv = 1.0f / red[0];
    for (int t = threadIdx.x; t < valid; t += blockDim.x) p[t] *= inv;
    for (int t = valid + threadIdx.x; t < TT; t += blockDim.x) p[t] = 0.0f;
}

// ---------------- host side ----------------------------------------------------
static float* sym_addr(const void* sym)
{
    void* p = nullptr;
    cudaGetSymbolAddress(&p, sym);
    return (float*)p;
}

static void run_gemm(const float* A, const float* B, float* C,
                     int M, int N, int K, int lda, int ldb, int ldc,
                     int Z, int zInner,
                     long sAo, long sAi, long sBo, long sBi, long sCo, long sCi,
                     int transB, int accumulate)
{
    dim3 grid(N / BN, M / BM, Z);
    gemm_kernel<<<grid, 256>>>(A, B, C, M, N, K, lda, ldb, ldc,
                               zInner, sAo, sAi, sBo, sBi, sCo, sCi,
                               transB, accumulate);
}

extern "C" void kernel_launch(void* const* d_in, const int* in_sizes, int n_in,
                              void* d_out, int out_size)
{
    const float* x       = (const float*)d_in[0];
    const float* W_DKV   = (const float*)d_in[1];
    const float* W_KRope = (const float*)d_in[2];
    const float* W_Q     = (const float*)d_in[3];
    const float* W_UK    = (const float*)d_in[4];
    const float* W_UV    = (const float*)d_in[5];
    const float* W_O     = (const float*)d_in[6];
    const float* kvw     = (const float*)d_in[7];
    const int*   offset  = (const int*)d_in[8];
    float* out = (float*)d_out;

    float* ckv    = sym_addr(g_ckv);
    float* krope  = sym_addr(g_krope);
    float* q      = sym_addr(g_q);
    float* qabs   = sym_addr(g_qabs);
    float* scores = sym_addr(g_scores);
    float* ctxlat = sym_addr(g_ctxlat);
    float* ctx    = sym_addr(g_ctx);

    // 1) c_kv raw = x @ W_DKV^T   [4096, 512]
    run_gemm(x, W_DKV, ckv, ROWS, LL, DIN, DIN, DIN, LL,
             1, 1, 0, 0, 0, 0, 0, 0, /*transB=*/1, 0);
    // 1b) rmsnorm rows
    rmsnorm_kernel<<<ROWS, 128>>>(ckv, kvw);

    // 2) k_rope raw = x @ W_KRope^T  [4096, 1024] (row=b*S+s, col=h*64+r)
    run_gemm(x, W_KRope, krope, ROWS, HH * RD, DIN, DIN, DIN, HH * RD,
             1, 1, 0, 0, 0, 0, 0, 0, 1, 0);
    // 2b) rope in place on k_rope
    {
        long total = (long)ROWS * HH * HALF_RD;
        int blocks = (int)((total + 255) / 256);
        rope_kernel<<<blocks, 256>>>(krope, HH * RD, 0, offset);
    }

    // 3) q_total = x @ W_Q^T  [4096, 3072]
    run_gemm(x, W_Q, q, ROWS, DOUT + HH * RD, DIN, DIN, DIN, DOUT + HH * RD,
             1, 1, 0, 0, 0, 0, 0, 0, 1, 0);
    // 3b) rope on q_rope columns [2048, 3072)
    {
        long total = (long)ROWS * HH * HALF_RD;
        int blocks = (int)((total + 255) / 256);
        rope_kernel<<<blocks, 256>>>(q, DOUT + HH * RD, DOUT, offset);
    }

    // 4) q_abs[b,s,h,l] = sum_d q_content[b,s,h*128+d] * W_UK[h*128+d, l]
    //    batched over h (Z=16): A=q + h*128 (lda 3072), B=W_UK + h*128*512 (ldb 512, nn),
    //    C=qabs + h*512 (ldc 8192)
    run_gemm(q, W_UK, qabs, ROWS, LL, HD,
             DOUT + HH * RD, LL, HH * LL,
             HH, 1,
             /*sAo=*/HD, 0, /*sBo=*/(long)HD * LL, 0, /*sCo=*/LL, 0,
             /*transB=*/0, 0);

    // 5) scores[z=(b*16+h)] = q_abs_slice @ c_kv_slice^T   (S x T, K=512)
    run_gemm(qabs, ckv, scores, SS, TT, LL,
             HH * LL, LL, TT,
             BB * HH, HH,
             /*sAo(b)=*/(long)SS * HH * LL, /*sAi(h)=*/LL,
             /*sBo(b)=*/(long)SS * LL,      /*sBi(h)=*/0,
             /*sCo(b)=*/(long)HH * SS * TT, /*sCi(h)=*/(long)SS * TT,
             /*transB=*/1, 0);

    // 5b) scores += q_rope_slice @ k_rope_slice^T  (K=64)
    run_gemm(q + DOUT, krope, scores, SS, TT, RD,
             DOUT + HH * RD, HH * RD, TT,
             BB * HH, HH,
             /*sAo(b)=*/(long)SS * (DOUT + HH * RD), /*sAi(h)=*/RD,
             /*sBo(b)=*/(long)SS * HH * RD,          /*sBi(h)=*/RD,
             /*sCo(b)=*/(long)HH * SS * TT,          /*sCi(h)=*/(long)SS * TT,
             /*transB=*/1, /*accumulate=*/1);

    // 6) masked scaled softmax per row
    softmax_kernel<<<BB * HH * SS, 256>>>(scores, offset);

    // 7) ctx_lat[b,s,h,l] = attn @ c_kv  (S x L, K=T)
    run_gemm(scores, ckv, ctxlat, SS, LL, TT,
             TT, LL, HH * LL,
             BB * HH, HH,
             /*sAo(b)=*/(long)HH * SS * TT, /*sAi(h)=*/(long)SS * TT,
             /*sBo(b)=*/(long)SS * LL,      /*sBi(h)=*/0,
             /*sCo(b)=*/(long)SS * HH * LL, /*sCi(h)=*/LL,
             /*transB=*/0, 0);

    // 8) ctx[b,s,h*128+d] = sum_l ctx_lat[b,s,h,l] * W_UV[h*128+d, l]
    //    batched over h: A=ctxlat + h*512 (lda 8192), B=W_UV + h*128*512 (ldb 512, nt),
    //    C=ctx + h*128 (ldc 2048). N=128.
    run_gemm(ctxlat, W_UV, ctx, ROWS, HD, LL,
             HH * LL, LL, DOUT,
             HH, 1,
             /*sAo=*/LL, 0, /*sBo=*/(long)HD * LL, 0, /*sCo=*/HD, 0,
             /*transB=*/1, 0);

    // 9) out = ctx @ W_O^T  [4096, 2048]
    run_gemm(ctx, W_O, out, ROWS, DIN, DOUT,
             DOUT, DOUT, DIN,
             1, 1, 0, 0, 0, 0, 0, 0, /*transB=*/1, 0);
}

// round 3
// speedup vs baseline: 1.7710x; 1.7710x over previous
#include <cuda_runtime.h>
#include <cuda_bf16.h>
#include <math.h>
#include <stdint.h>

// Problem constants
#define BB 2
#define SS 2048
#define TT 2048
#define DIN 2048
#define DOUT 2048
#define HH 16
#define RD 64
#define HALF_RD 32
#define LL 512
#define HD 128
#define ROWS (BB*SS)          // 4096

// ---------------- device scratch (static; no allocations) ---------------------
__device__ __align__(128) float g_ckv  [BB*SS*LL];
__device__ __align__(128) float g_ckvT [BB*LL*SS];
__device__ __align__(128) float g_krope[BB*SS*HH*RD];
__device__ __align__(128) float g_q    [BB*SS*(DOUT+HH*RD)];
__device__ __align__(128) float g_qabs [ROWS*HH*LL];
__device__ __align__(128) float g_wukT [DOUT*LL];
__device__ __align__(128) float g_scores[(long)BB*HH*SS*TT];
__device__ __align__(128) float g_ctxlat[ROWS*HH*LL];
__device__ __align__(128) float g_ctx  [ROWS*DOUT];

// ================= helpers =====================================================
__device__ __forceinline__ float f2tf(float x) {
    uint32_t u; asm("cvt.rna.tf32.f32 %0, %1;" : "=r"(u) : "f"(x));
    return __uint_as_float(u);
}

__device__ __forceinline__ void mma_tf32(float* c, const uint32_t* a, const uint32_t* b) {
    asm volatile(
        "mma.sync.aligned.m16n8k8.row.col.f32.tf32.tf32.f32 "
        "{%0,%1,%2,%3}, {%4,%5,%6,%7}, {%8,%9}, {%0,%1,%2,%3};"
        : "+f"(c[0]), "+f"(c[1]), "+f"(c[2]), "+f"(c[3])
        : "r"(a[0]), "r"(a[1]), "r"(a[2]), "r"(a[3]), "r"(b[0]), "r"(b[1]));
}

// ================= TF32 mma.sync GEMM ==========================================
// C[m,n] (+)= sum_k A[m,k]*B[n,k]; A [M,K] lda, B [N,K] ldb (both K-contiguous).
// M,N multiples of 128; K multiple of 32. Batched over blockIdx.z via strides.
// PREC=1: single tf32 pass. PREC=3: tf32x3 (hi/lo split, near-fp32 accuracy).
#define ASZ (128*36)
#define BSZ (32*136)

template<int PREC>
__global__ void __launch_bounds__(256)
gemm_mma(const float* __restrict__ Ab, const float* __restrict__ Bb, float* __restrict__ Cb,
         int K, int lda, int ldb, int ldc,
         int zInner, long sAo, long sAi, long sBo, long sBi, long sCo, long sCi,
         int accumulate)
{
    extern __shared__ float sm[];
    float* Ah = sm;
    float* Bh = sm + 2 * ASZ;
    float* Al = (PREC == 3) ? (sm + 2 * ASZ + 2 * BSZ) : nullptr;
    float* Bl = (PREC == 3) ? (sm + 4 * ASZ + 2 * BSZ) : nullptr;

    const int tid  = threadIdx.x;
    const int lane = tid & 31;
    const int wid  = tid >> 5;
    const int gid  = lane >> 2;
    const int tig  = lane & 3;
    const int wm   = wid >> 2;   // 0..1
    const int wn   = wid & 3;    // 0..3

    const int z  = blockIdx.z;
    const int zo = z / zInner, zi = z % zInner;
    const int m0 = blockIdx.y * 128;
    const int n0 = blockIdx.x * 128;
    const float* A = Ab + zo * sAo + zi * sAi + (long)m0 * lda;
    const float* B = Bb + zo * sBo + zi * sBi + (long)n0 * ldb;
    float*       C = Cb + zo * sCo + zi * sCi;

    float acc[4][4][4];
    #pragma unroll
    for (int mt = 0; mt < 4; mt++)
        #pragma unroll
        for (int nt = 0; nt < 4; nt++)
            #pragma unroll
            for (int i = 0; i < 4; i++) acc[mt][nt][i] = 0.0f;

    float4 pA[4], pB[4];

    auto fetch = [&](int k0) {
        #pragma unroll
        for (int i = 0; i < 4; i++) {
            int f4 = tid + i * 256;
            int row = f4 >> 3, c4 = f4 & 7;
            pA[i] = *(const float4*)(A + (long)row * lda + k0 + c4 * 4);
            pB[i] = *(const float4*)(B + (long)row * ldb + k0 + c4 * 4);
        }
    };
    auto commit = [&](int buf) {
        #pragma unroll
        for (int i = 0; i < 4; i++) {
            int f4 = tid + i * 256;
            int row = f4 >> 3, c4 = f4 & 7;
            float4 v = pA[i];
            float4 h;
            h.x = f2tf(v.x); h.y = f2tf(v.y); h.z = f2tf(v.z); h.w = f2tf(v.w);
            *(float4*)(Ah + buf * ASZ + row * 36 + c4 * 4) = h;
            if (PREC == 3) {
                float4 l;
                l.x = f2tf(v.x - h.x); l.y = f2tf(v.y - h.y);
                l.z = f2tf(v.z - h.z); l.w = f2tf(v.w - h.w);
                *(float4*)(Al + buf * ASZ + row * 36 + c4 * 4) = l;
            }
            float4 w = pB[i];
            float wh[4] = { f2tf(w.x), f2tf(w.y), f2tf(w.z), f2tf(w.w) };
            float wraw[4] = { w.x, w.y, w.z, w.w };
            #pragma unroll
            for (int j = 0; j < 4; j++) {
                Bh[buf * BSZ + (c4 * 4 + j) * 136 + row] = wh[j];
                if (PREC == 3)
                    Bl[buf * BSZ + (c4 * 4 + j) * 136 + row] = f2tf(wraw[j] - wh[j]);
            }
        }
    };

    auto compute = [&](int buf) {
        const float* Ab_ = Ah + buf * ASZ;
        const float* Bb_ = Bh + buf * BSZ;
        #pragma unroll
        for (int ks = 0; ks < 4; ks++) {
            uint32_t ah[4][4], bh[4][2];
            #pragma unroll
            for (int mt = 0; mt < 4; mt++) {
                int r0 = wm * 64 + mt * 16 + gid;
                int cl = ks * 8 + tig;
                ah[mt][0] = __float_as_uint(Ab_[r0 * 36 + cl]);
                ah[mt][1] = __float_as_uint(Ab_[(r0 + 8) * 36 + cl]);
                ah[mt][2] = __float_as_uint(Ab_[r0 * 36 + cl + 4]);
                ah[mt][3] = __float_as_uint(Ab_[(r0 + 8) * 36 + cl + 4]);
            }
            #pragma unroll
            for (int nt = 0; nt < 4; nt++) {
                int n = wn * 32 + nt * 8 + gid;
                bh[nt][0] = __float_as_uint(Bb_[(ks * 8 + tig) * 136 + n]);
                bh[nt][1] = __float_as_uint(Bb_[(ks * 8 + tig + 4) * 136 + n]);
            }
            #pragma unroll
            for (int mt = 0; mt < 4; mt++)
                #pragma unroll
                for (int nt = 0; nt < 4; nt++)
                    mma_tf32(acc[mt][nt], ah[mt], bh[nt]);

            if (PREC == 3) {
                const float* Al_ = Al + buf * ASZ;
                const float* Bl_ = Bl + buf * BSZ;
                uint32_t al[4][4], bl[4][2];
                #pragma unroll
                for (int mt = 0; mt < 4; mt++) {
                    int r0 = wm * 64 + mt * 16 + gid;
                    int cl = ks * 8 + tig;
                    al[mt][0] = __float_as_uint(Al_[r0 * 36 + cl]);
                    al[mt][1] = __float_as_uint(Al_[(r0 + 8) * 36 + cl]);
                    al[mt][2] = __float_as_uint(Al_[r0 * 36 + cl + 4]);
                    al[mt][3] = __float_as_uint(Al_[(r0 + 8) * 36 + cl + 4]);
                }
                #pragma unroll
                for (int nt = 0; nt < 4; nt++) {
                    int n = wn * 32 + nt * 8 + gid;
                    bl[nt][0] = __float_as_uint(Bl_[(ks * 8 + tig) * 136 + n]);
                    bl[nt][1] = __float_as_uint(Bl_[(ks * 8 + tig + 4) * 136 + n]);
                }
                #pragma unroll
                for (int mt = 0; mt < 4; mt++)
                    #pragma unroll
                    for (int nt = 0; nt < 4; nt++) {
                        mma_tf32(acc[mt][nt], ah[mt], bl[nt]);
                        mma_tf32(acc[mt][nt], al[mt], bh[nt]);
                    }
            }
        }
    };

    const int NC = K >> 5;
    fetch(0);
    commit(0);
    __syncthreads();
    for (int c = 0; c < NC; c++) {
        if (c + 1 < NC) fetch((c + 1) << 5);
        compute(c & 1);
        if (c + 1 < NC) commit((c + 1) & 1);
        __syncthreads();
    }

    // epilogue
    #pragma unroll
    for (int mt = 0; mt < 4; mt++) {
        #pragma unroll
        for (int nt = 0; nt < 4; nt++) {
            int r  = m0 + wm * 64 + mt * 16 + gid;
            int cc = n0 + wn * 32 + nt * 8 + tig * 2;
            float2* p0 = (float2*)&C[(long)r * ldc + cc];
            float2* p1 = (float2*)&C[(long)(r + 8) * ldc + cc];
            float2 v0 = { acc[mt][nt][0], acc[mt][nt][1] };
            float2 v1 = { acc[mt][nt][2], acc[mt][nt][3] };
            if (accumulate) {
                float2 o0 = *p0, o1 = *p1;
                v0.x += o0.x; v0.y += o0.y;
                v1.x += o1.x; v1.y += o1.y;
            }
            *p0 = v0;
            *p1 = v1;
        }
    }
}

// ================= small kernels ===============================================
__global__ void rmsnorm_kernel(float* __restrict__ data, const float* __restrict__ w)
{
    const int row = blockIdx.x;
    float* p = data + (long)row * LL;
    float ss = 0.0f;
    for (int i = threadIdx.x; i < LL; i += blockDim.x) { float v = p[i]; ss += v * v; }
    __shared__ float red[32];
    for (int o = 16; o; o >>= 1) ss += __shfl_xor_sync(0xffffffffu, ss, o);
    if ((threadIdx.x & 31) == 0) red[threadIdx.x >> 5] = ss;
    __syncthreads();
    if (threadIdx.x < 32) {
        float v = (threadIdx.x < (blockDim.x >> 5)) ? red[threadIdx.x] : 0.0f;
        for (int o = 16; o; o >>= 1) v += __shfl_xor_sync(0xffffffffu, v, o);
        if (threadIdx.x == 0) red[0] = v;
    }
    __syncthreads();
    float rstd = rsqrtf(red[0] / (float)LL + 1e-6f);
    for (int i = threadIdx.x; i < LL; i += blockDim.x) p[i] = p[i] * rstd * w[i];
}

__global__ void rope_kernel(float* __restrict__ data, int ld, int colbase,
                            const int* __restrict__ offset_p)
{
    long idx = (long)blockIdx.x * blockDim.x + threadIdx.x;
    const long total = (long)ROWS * HH * HALF_RD;
    if (idx >= total) return;
    int  j   = (int)(idx % HALF_RD);
    int  h   = (int)((idx / HALF_RD) % HH);
    long row = idx / (HALF_RD * HH);
    int  s   = (int)(row % SS);
    float pos = (float)(s + *offset_p);
    float inv = expf(-(float)j * (logf(10000.0f) / 32.0f));
    float ang = pos * inv;
    float c  = cosf(ang);
    float si = sinf(ang);
    float* p = data + row * (long)ld + colbase + h * RD;
    float x1 = p[j], x2 = p[j + HALF_RD];
    p[j]           = x1 * c - x2 * si;
    p[j + HALF_RD] = x2 * c + x1 * si;
}

__global__ void softmax_kernel(float* __restrict__ scores, const int* __restrict__ offset_p)
{
    const long row = blockIdx.x;            // (b*H+h)*S + s
    const int  s   = (int)(row % SS);
    int valid = s + *offset_p + 1;
    if (valid > TT) valid = TT;
    float* p = scores + row * (long)TT;
    const float scale = rsqrtf((float)(HD + RD));

    float m = -INFINITY;
    for (int t = threadIdx.x; t < valid; t += blockDim.x) m = fmaxf(m, p[t] * scale);
    __shared__ float red[32];
    for (int o = 16; o; o >>= 1) m = fmaxf(m, __shfl_xor_sync(0xffffffffu, m, o));
    if ((threadIdx.x & 31) == 0) red[threadIdx.x >> 5] = m;
    __syncthreads();
    if (threadIdx.x < 32) {
        float v = (threadIdx.x < (blockDim.x >> 5)) ? red[threadIdx.x] : -INFINITY;
        for (int o = 16; o; o >>= 1) v = fmaxf(v, __shfl_xor_sync(0xffffffffu, v, o));
        if (threadIdx.x == 0) red[0] = v;
    }
    __syncthreads();
    m = red[0];
    __syncthreads();

    float sum = 0.0f;
    for (int t = threadIdx.x; t < valid; t += blockDim.x) {
        float e = expf(p[t] * scale - m);
        p[t] = e;
        sum += e;
    }
    for (int o = 16; o; o >>= 1) sum += __shfl_xor_sync(0xffffffffu, sum, o);
    if ((threadIdx.x & 31) == 0) red[threadIdx.x >> 5] = sum;
    __syncthreads();
    if (threadIdx.x < 32) {
        float v = (threadIdx.x < (blockDim.x >> 5)) ? red[threadIdx.x] : 0.0f;
        for (int o = 16; o; o >>= 1) v += __shfl_xor_sync(0xffffffffu, v, o);
        if (threadIdx.x == 0) red[0] = v;
    }
    __syncthreads();
    float inv = 1.0f / red[0];
    for (int t = threadIdx.x; t < valid; t += blockDim.x) p[t] *= inv;
    for (int t = valid + threadIdx.x; t < TT; t += blockDim.x) p[t] = 0.0f;
}

// 32x32 tiled transpose: out[c, r] = in[r, c], batched over z
__global__ void transpose_kernel(const float* __restrict__ in, float* __restrict__ out,
                                 int R, int Cc, long sIn, long sOut)
{
    __shared__ float t[32][33];
    const float* ip = in + blockIdx.z * sIn;
    float* op = out + blockIdx.z * sOut;
    const int c0 = blockIdx.x * 32, r0 = blockIdx.y * 32;
    for (int i = threadIdx.y; i < 32; i += 8)
        t[i][threadIdx.x] = ip[(long)(r0 + i) * Cc + c0 + threadIdx.x];
    __syncthreads();
    for (int i = threadIdx.y; i < 32; i += 8)
        op[(long)(c0 + i) * R + r0 + threadIdx.x] = t[threadIdx.x][i];
}

// ================= host side ====================================================
static float* sym_addr(const void* sym)
{
    void* p = nullptr;
    cudaGetSymbolAddress(&p, sym);
    return (float*)p;
}

#define SMEM1 (2*(ASZ+BSZ)*4)   // 71680
#define SMEM3 (4*(ASZ+BSZ)*4)   // 143360

static void run_gemm(const float* A, const float* B, float* C,
                     int M, int N, int K, int lda, int ldb, int ldc,
                     int Z, int zInner,
                     long sAo, long sAi, long sBo, long sBi, long sCo, long sCi,
                     int accumulate, int prec)
{
    dim3 grid(N / 128, M / 128, Z);
    if (prec == 3)
        gemm_mma<3><<<grid, 256, SMEM3>>>(A, B, C, K, lda, ldb, ldc,
                                          zInner, sAo, sAi, sBo, sBi, sCo, sCi, accumulate);
    else
        gemm_mma<1><<<grid, 256, SMEM1>>>(A, B, C, K, lda, ldb, ldc,
                                          zInner, sAo, sAi, sBo, sBi, sCo, sCi, accumulate);
}

extern "C" void kernel_launch(void* const* d_in, const int* in_sizes, int n_in,
                              void* d_out, int out_size)
{
    const float* x       = (const float*)d_in[0];
    const float* W_DKV   = (const float*)d_in[1];
    const float* W_KRope = (const float*)d_in[2];
    const float* W_Q     = (const float*)d_in[3];
    const float* W_UK    = (const float*)d_in[4];
    const float* W_UV    = (const float*)d_in[5];
    const float* W_O     = (const float*)d_in[6];
    const float* kvw     = (const float*)d_in[7];
    const int*   offset  = (const int*)d_in[8];
    float* out = (float*)d_out;

    static int s_init = 0;
    if (!s_init) {
        cudaFuncSetAttribute(gemm_mma<1>, cudaFuncAttributeMaxDynamicSharedMemorySize, SMEM1);
        cudaFuncSetAttribute(gemm_mma<3>, cudaFuncAttributeMaxDynamicSharedMemorySize, SMEM3);
        s_init = 1;
    }

    float* ckv    = sym_addr(g_ckv);
    float* ckvT   = sym_addr(g_ckvT);
    float* krope  = sym_addr(g_krope);
    float* q      = sym_addr(g_q);
    float* qabs   = sym_addr(g_qabs);
    float* wukT   = sym_addr(g_wukT);
    float* scores = sym_addr(g_scores);
    float* ctxlat = sym_addr(g_ctxlat);
    float* ctx    = sym_addr(g_ctx);

    // 1) c_kv = rmsnorm(x @ W_DKV^T)  [critical: feeds ctx_lat directly]
    run_gemm(x, W_DKV, ckv, ROWS, LL, DIN, DIN, DIN, LL,
             1, 1, 0, 0, 0, 0, 0, 0, 0, 3);
    rmsnorm_kernel<<<ROWS, 128>>>(ckv, kvw);
    {
        dim3 grid(LL / 32, SS / 32, BB), block(32, 8);
        transpose_kernel<<<grid, block>>>(ckv, ckvT, SS, LL,
                                          (long)SS * LL, (long)LL * SS);
    }

    // 2) k_rope = rope(x @ W_KRope^T)   [pre-softmax]
    run_gemm(x, W_KRope, krope, ROWS, HH * RD, DIN, DIN, DIN, HH * RD,
             1, 1, 0, 0, 0, 0, 0, 0, 0, 1);
    {
        long total = (long)ROWS * HH * HALF_RD;
        rope_kernel<<<(int)((total + 255) / 256), 256>>>(krope, HH * RD, 0, offset);
    }

    // 3) q_total = x @ W_Q^T   [pre-softmax]
    run_gemm(x, W_Q, q, ROWS, DOUT + HH * RD, DIN, DIN, DIN, DOUT + HH * RD,
             1, 1, 0, 0, 0, 0, 0, 0, 0, 1);
    {
        long total = (long)ROWS * HH * HALF_RD;
        rope_kernel<<<(int)((total + 255) / 256), 256>>>(q, DOUT + HH * RD, DOUT, offset);
    }

    // W_UK^T per head
    {
        dim3 grid(LL / 32, HD / 32, HH), block(32, 8);
        transpose_kernel<<<grid, block>>>(W_UK, wukT, HD, LL,
                                          (long)HD * LL, (long)LL * HD);
    }

    // 4) q_abs  [pre-softmax]
    run_gemm(q, wukT, qabs, ROWS, LL, HD,
             DOUT + HH * RD, HD, HH * LL,
             HH, HH,
             0, HD, 0, (long)LL * HD, 0, LL, 0, 1);

    // 5a) scores = q_rope @ k_rope^T  (K=64)  [pre-softmax]
    run_gemm(q + DOUT, krope, scores, SS, TT, RD,
             DOUT + HH * RD, HH * RD, TT,
             BB * HH, HH,
             (long)SS * (DOUT + HH * RD), RD,
             (long)SS * HH * RD, RD,
             (long)HH * SS * TT, (long)SS * TT, 0, 1);

    // 5b) scores += q_abs @ c_kv^T  (K=512)  [pre-softmax]
    run_gemm(qabs, ckv, scores, SS, TT, LL,
             HH * LL, LL, TT,
             BB * HH, HH,
             (long)SS * HH * LL, LL,
             (long)SS * LL, 0,
             (long)HH * SS * TT, (long)SS * TT, 1, 1);

    // 6) masked scaled softmax
    softmax_kernel<<<BB * HH * SS, 256>>>(scores, offset);

    // 7) ctx_lat = attn @ c_kv (via ckvT)  [critical]
    run_gemm(scores, ckvT, ctxlat, SS, LL, TT,
             TT, SS, HH * LL,
             BB * HH, HH,
             (long)HH * SS * TT, (long)SS * TT,
             (long)LL * SS, 0,
             (long)SS * HH * LL, LL, 0, 3);

    // 8) ctx = ctx_lat @ W_UV^T per head  [critical]
    run_gemm(ctxlat, W_UV, ctx, ROWS, HD, LL,
             HH * LL, LL, DOUT,
             HH, HH,
             0, LL, 0, (long)HD * LL, 0, HD, 0, 3);

    // 9) out = ctx @ W_O^T  [critical]
    run_gemm(ctx, W_O, out, ROWS, DIN, DOUT,
             DOUT, DOUT, DIN,
             1, 1, 0, 0, 0, 0, 0, 0, 0, 3);
}

// round 4
// speedup vs baseline: 2.9049x; 1.6403x over previous
#include <cuda_runtime.h>
#include <cuda_bf16.h>
#include <math.h>
#include <stdint.h>

// Problem constants
#define BB 2
#define SS 2048
#define TT 2048
#define DIN 2048
#define DOUT 2048
#define HH 16
#define RD 64
#define HALF_RD 32
#define LL 512
#define HD 128
#define ROWS (BB*SS)          // 4096

// ---------------- device scratch (static; no allocations) ---------------------
__device__ __align__(128) float g_ckv  [BB*SS*LL];
__device__ __align__(128) float g_ckvT [BB*LL*SS];
__device__ __align__(128) float g_krope[BB*SS*HH*RD];
__device__ __align__(128) float g_q    [BB*SS*(DOUT+HH*RD)];
__device__ __align__(128) float g_qabs [ROWS*HH*LL];
__device__ __align__(128) float g_wukT [DOUT*LL];
__device__ __align__(128) float g_scores[(long)BB*HH*SS*TT];
__device__ __align__(128) float g_ctxlat[ROWS*HH*LL];
__device__ __align__(128) float g_ctx  [ROWS*DOUT];

// ================= helpers =====================================================
__device__ __forceinline__ float f2tf(float x) {
    uint32_t u; asm("cvt.rna.tf32.f32 %0, %1;" : "=r"(u) : "f"(x));
    return __uint_as_float(u);
}
__device__ __forceinline__ uint32_t smem_u32(const void* p) {
    uint32_t a;
    asm("{ .reg .u64 t; cvta.to.shared.u64 t, %1; cvt.u32.u64 %0, t; }" : "=r"(a) : "l"(p));
    return a;
}
__device__ __forceinline__ void cp16(uint32_t dst, const void* src) {
    asm volatile("cp.async.cg.shared.global [%0], [%1], 16;" :: "r"(dst), "l"(src));
}
#define CP_COMMIT() asm volatile("cp.async.commit_group;" ::: "memory")
#define CP_WAIT2()  asm volatile("cp.async.wait_group 2;"  ::: "memory")

__device__ __forceinline__ void mma_tf32(float* c, const uint32_t* a, const uint32_t* b) {
    asm volatile(
        "mma.sync.aligned.m16n8k8.row.col.f32.tf32.tf32.f32 "
        "{%0,%1,%2,%3}, {%4,%5,%6,%7}, {%8,%9}, {%0,%1,%2,%3};"
        : "+f"(c[0]), "+f"(c[1]), "+f"(c[2]), "+f"(c[3])
        : "r"(a[0]), "r"(a[1]), "r"(a[2]), "r"(a[3]), "r"(b[0]), "r"(b[1]));
}

// ================= TF32 mma.sync GEMM with cp.async pipeline ===================
// C[m,n] (+)= sum_k A[m,k]*B[n,k]; A [M,K] lda, B [N,K] ldb (both K-contiguous).
// M,N multiples of 128; K multiple of 16 and >= 48 (all call sites have K>=64).
// Batched over blockIdx.z via strides. PREC=1: tf32. PREC=3: tf32x3 (hi/lo).
// SMEM: 4 stages x (A 128x16 pad20 + B 128x16 pad20) floats.
#define STAGEF 5120                 // floats per stage (2560 A + 2560 B)
#define GEMM_SMEM (4*STAGEF*4)      // 81920 bytes

template<int PREC, int MINCTA>
__global__ void __launch_bounds__(256, MINCTA)
gemm_cp(const float* __restrict__ Ab, const float* __restrict__ Bb, float* __restrict__ Cb,
        int K, int lda, int ldb, int ldc,
        int zInner, long sAo, long sAi, long sBo, long sBi, long sCo, long sCi,
        int accumulate)
{
    extern __shared__ float sm[];

    const int tid  = threadIdx.x;
    const int lane = tid & 31;
    const int wid  = tid >> 5;
    const int gid  = lane >> 2;
    const int tig  = lane & 3;
    const int wm   = wid >> 2;   // 0..1
    const int wn   = wid & 3;    // 0..3

    const int z  = blockIdx.z;
    const int zo = z / zInner, zi = z % zInner;
    const int m0 = blockIdx.y * 128;
    const int n0 = blockIdx.x * 128;
    const float* A = Ab + zo * sAo + zi * sAi + (long)m0 * lda;
    const float* B = Bb + zo * sBo + zi * sBi + (long)n0 * ldb;
    float*       C = Cb + zo * sCo + zi * sCi;

    const uint32_t sbase = smem_u32(sm);

    float acc[4][4][4];
    #pragma unroll
    for (int mt = 0; mt < 4; mt++)
        #pragma unroll
        for (int nt = 0; nt < 4; nt++)
            #pragma unroll
            for (int i = 0; i < 4; i++) acc[mt][nt][i] = 0.0f;

    // stage copy: 128x16 A + 128x16 B, 2 float4 per thread per tile
    const int crow = tid >> 2;          // 0..63
    const int cc4  = tid & 3;           // 0..3
    auto issue = [&](int c) {
        const int k0  = c << 4;
        const uint32_t st = sbase + (uint32_t)(c & 3) * (STAGEF * 4);
        #pragma unroll
        for (int i = 0; i < 2; i++) {
            int row = crow + i * 64;
            uint32_t d = st + (uint32_t)(row * 20 + cc4 * 4) * 4;
            cp16(d,             A + (long)row * lda + k0 + cc4 * 4);
            cp16(d + 2560 * 4,  B + (long)row * ldb + k0 + cc4 * 4);
        }
    };

    auto compute = [&](int c) {
        const float* As = sm + (c & 3) * STAGEF;
        const float* Bs = As + 2560;
        #pragma unroll
        for (int ks = 0; ks < 2; ks++) {
            uint32_t ah[4][4], bh[4][2];
            uint32_t al[4][4], bl[4][2];
            #pragma unroll
            for (int mt = 0; mt < 4; mt++) {
                const int r0 = wm * 64 + mt * 16 + gid;
                const int cl = ks * 8 + tig;
                float r0c0 = As[r0 * 20 + cl];
                float r1c0 = As[(r0 + 8) * 20 + cl];
                float r0c1 = As[r0 * 20 + cl + 4];
                float r1c1 = As[(r0 + 8) * 20 + cl + 4];
                float h0 = f2tf(r0c0), h1 = f2tf(r1c0), h2 = f2tf(r0c1), h3 = f2tf(r1c1);
                ah[mt][0] = __float_as_uint(h0);
                ah[mt][1] = __float_as_uint(h1);
                ah[mt][2] = __float_as_uint(h2);
                ah[mt][3] = __float_as_uint(h3);
                if (PREC == 3) {
                    al[mt][0] = __float_as_uint(f2tf(r0c0 - h0));
                    al[mt][1] = __float_as_uint(f2tf(r1c0 - h1));
                    al[mt][2] = __float_as_uint(f2tf(r0c1 - h2));
                    al[mt][3] = __float_as_uint(f2tf(r1c1 - h3));
                }
            }
            #pragma unroll
            for (int nt = 0; nt < 4; nt++) {
                const int n = wn * 32 + nt * 8 + gid;
                float w0 = Bs[n * 20 + ks * 8 + tig];
                float w1 = Bs[n * 20 + ks * 8 + tig + 4];
                float h0 = f2tf(w0), h1 = f2tf(w1);
                bh[nt][0] = __float_as_uint(h0);
                bh[nt][1] = __float_as_uint(h1);
                if (PREC == 3) {
                    bl[nt][0] = __float_as_uint(f2tf(w0 - h0));
                    bl[nt][1] = __float_as_uint(f2tf(w1 - h1));
                }
            }
            #pragma unroll
            for (int mt = 0; mt < 4; mt++)
                #pragma unroll
                for (int nt = 0; nt < 4; nt++)
                    mma_tf32(acc[mt][nt], ah[mt], bh[nt]);
            if (PREC == 3) {
                #pragma unroll
                for (int mt = 0; mt < 4; mt++)
                    #pragma unroll
                    for (int nt = 0; nt < 4; nt++) {
                        mma_tf32(acc[mt][nt], ah[mt], bl[nt]);
                        mma_tf32(acc[mt][nt], al[mt], bh[nt]);
                    }
            }
        }
    };

    const int NC = K >> 4;              // K/16, >= 4 at all call sites
    issue(0); CP_COMMIT();
    issue(1); CP_COMMIT();
    issue(2); CP_COMMIT();
    for (int c = 0; c < NC; c++) {
        CP_WAIT2();
        __syncthreads();
        if (c + 3 < NC) issue(c + 3);
        CP_COMMIT();
        compute(c);
    }

    // epilogue
    #pragma unroll
    for (int mt = 0; mt < 4; mt++) {
        #pragma unroll
        for (int nt = 0; nt < 4; nt++) {
            int r  = m0 + wm * 64 + mt * 16 + gid;
            int cc = n0 + wn * 32 + nt * 8 + tig * 2;
            float2* p0 = (float2*)&C[(long)r * ldc + cc];
            float2* p1 = (float2*)&C[(long)(r + 8) * ldc + cc];
            float2 v0 = { acc[mt][nt][0], acc[mt][nt][1] };
            float2 v1 = { acc[mt][nt][2], acc[mt][nt][3] };
            if (accumulate) {
                float2 o0 = *p0, o1 = *p1;
                v0.x += o0.x; v0.y += o0.y;
                v1.x += o1.x; v1.y += o1.y;
            }
            *p0 = v0;
            *p1 = v1;
        }
    }
}

// ================= small kernels ===============================================
__global__ void rmsnorm_kernel(float* __restrict__ data, const float* __restrict__ w)
{
    const int row = blockIdx.x;
    float* p = data + (long)row * LL;
    float ss = 0.0f;
    for (int i = threadIdx.x; i < LL; i += blockDim.x) { float v = p[i]; ss += v * v; }
    __shared__ float red[32];
    for (int o = 16; o; o >>= 1) ss += __shfl_xor_sync(0xffffffffu, ss, o);
    if ((threadIdx.x & 31) == 0) red[threadIdx.x >> 5] = ss;
    __syncthreads();
    if (threadIdx.x < 32) {
        float v = (threadIdx.x < (blockDim.x >> 5)) ? red[threadIdx.x] : 0.0f;
        for (int o = 16; o; o >>= 1) v += __shfl_xor_sync(0xffffffffu, v, o);
        if (threadIdx.x == 0) red[0] = v;
    }
    __syncthreads();
    float rstd = rsqrtf(red[0] / (float)LL + 1e-6f);
    for (int i = threadIdx.x; i < LL; i += blockDim.x) p[i] = p[i] * rstd * w[i];
}

__global__ void rope_kernel(float* __restrict__ data, int ld, int colbase,
                            const int* __restrict__ offset_p)
{
    long idx = (long)blockIdx.x * blockDim.x + threadIdx.x;
    const long total = (long)ROWS * HH * HALF_RD;
    if (idx >= total) return;
    int  j   = (int)(idx % HALF_RD);
    int  h   = (int)((idx / HALF_RD) % HH);
    long row = idx / (HALF_RD * HH);
    int  s   = (int)(row % SS);
    float pos = (float)(s + *offset_p);
    float inv = expf(-(float)j * (logf(10000.0f) / 32.0f));
    float ang = pos * inv;
    float c  = cosf(ang);
    float si = sinf(ang);
    float* p = data + row * (long)ld + colbase + h * RD;
    float x1 = p[j], x2 = p[j + HALF_RD];
    p[j]           = x1 * c - x2 * si;
    p[j + HALF_RD] = x2 * c + x1 * si;
}

// register-resident masked scaled softmax; 256 threads, 8 els/thread (T=2048)
__global__ void __launch_bounds__(256)
softmax_kernel(float* __restrict__ scores, const int* __restrict__ offset_p)
{
    const long row = blockIdx.x;            // (b*H+h)*S + s
    const int  s   = (int)(row % SS);
    int valid = s + *offset_p + 1;
    if (valid > TT) valid = TT;
    float* p = scores + row * (long)TT;
    const float scale = rsqrtf((float)(HD + RD));
    const int tid = threadIdx.x;

    float4 v[2];
    float m = -INFINITY;
    #pragma unroll
    for (int i = 0; i < 2; i++) {
        int e0 = (tid + i * 256) * 4;
        v[i] = *(const float4*)(p + e0);
        float* f = (float*)&v[i];
        #pragma unroll
        for (int j = 0; j < 4; j++) {
            f[j] = (e0 + j < valid) ? f[j] * scale : -INFINITY;
            m = fmaxf(m, f[j]);
        }
    }
    __shared__ float red[32];
    for (int o = 16; o; o >>= 1) m = fmaxf(m, __shfl_xor_sync(0xffffffffu, m, o));
    if ((tid & 31) == 0) red[tid >> 5] = m;
    __syncthreads();
    if (tid < 32) {
        float t = (tid < 8) ? red[tid] : -INFINITY;
        for (int o = 16; o; o >>= 1) t = fmaxf(t, __shfl_xor_sync(0xffffffffu, t, o));
        if (tid == 0) red[0] = t;
    }
    __syncthreads();
    m = red[0];
    __syncthreads();

    float sum = 0.0f;
    #pragma unroll
    for (int i = 0; i < 2; i++) {
        float* f = (float*)&v[i];
        #pragma unroll
        for (int j = 0; j < 4; j++) {
            float e = (f[j] == -INFINITY) ? 0.0f : expf(f[j] - m);
            f[j] = e;
            sum += e;
        }
    }
    for (int o = 16; o; o >>= 1) sum += __shfl_xor_sync(0xffffffffu, sum, o);
    if ((tid & 31) == 0) red[tid >> 5] = sum;
    __syncthreads();
    if (tid < 32) {
        float t = (tid < 8) ? red[tid] : 0.0f;
        for (int o = 16; o; o >>= 1) t += __shfl_xor_sync(0xffffffffu, t, o);
        if (tid == 0) red[0] = t;
    }
    __syncthreads();
    float inv = 1.0f / red[0];
    #pragma unroll
    for (int i = 0; i < 2; i++) {
        float* f = (float*)&v[i];
        #pragma unroll
        for (int j = 0; j < 4; j++) f[j] *= inv;
        *(float4*)(p + (tid + i * 256) * 4) = v[i];
    }
}

// 32x32 tiled transpose: out[c, r] = in[r, c], batched over z
__global__ void transpose_kernel(const float* __restrict__ in, float* __restrict__ out,
                                 int R, int Cc, long sIn, long sOut)
{
    __shared__ float t[32][33];
    const float* ip = in + blockIdx.z * sIn;
    float* op = out + blockIdx.z * sOut;
    const int c0 = blockIdx.x * 32, r0 = blockIdx.y * 32;
    for (int i = threadIdx.y; i < 32; i += 8)
        t[i][threadIdx.x] = ip[(long)(r0 + i) * Cc + c0 + threadIdx.x];
    __syncthreads();
    for (int i = threadIdx.y; i < 32; i += 8)
        op[(long)(c0 + i) * R + r0 + threadIdx.x] = t[threadIdx.x][i];
}

// ================= host side ====================================================
static float* sym_addr(const void* sym)
{
    void* p = nullptr;
    cudaGetSymbolAddress(&p, sym);
    return (float*)p;
}

static void run_gemm(const float* A, const float* B, float* C,
                     int M, int N, int K, int lda, int ldb, int ldc,
                     int Z, int zInner,
                     long sAo, long sAi, long sBo, long sBi, long sCo, long sCi,
                     int accumulate, int prec)
{
    dim3 grid(N / 128, M / 128, Z);
    if (prec == 3)
        gemm_cp<3,1><<<grid, 256, GEMM_SMEM>>>(A, B, C, K, lda, ldb, ldc,
                                               zInner, sAo, sAi, sBo, sBi, sCo, sCi, accumulate);
    else
        gemm_cp<1,2><<<grid, 256, GEMM_SMEM>>>(A, B, C, K, lda, ldb, ldc,
                                               zInner, sAo, sAi, sBo, sBi, sCo, sCi, accumulate);
}

extern "C" void kernel_launch(void* const* d_in, const int* in_sizes, int n_in,
                              void* d_out, int out_size)
{
    const float* x       = (const float*)d_in[0];
    const float* W_DKV   = (const float*)d_in[1];
    const float* W_KRope = (const float*)d_in[2];
    const float* W_Q     = (const float*)d_in[3];
    const float* W_UK    = (const float*)d_in[4];
    const float* W_UV    = (const float*)d_in[5];
    const float* W_O     = (const float*)d_in[6];
    const float* kvw     = (const float*)d_in[7];
    const int*   offset  = (const int*)d_in[8];
    float* out = (float*)d_out;

    static int s_init = 0;
    if (!s_init) {
        cudaFuncSetAttribute((const void*)gemm_cp<1,2>, cudaFuncAttributeMaxDynamicSharedMemorySize, GEMM_SMEM);
        cudaFuncSetAttribute((const void*)gemm_cp<3,1>, cudaFuncAttributeMaxDynamicSharedMemorySize, GEMM_SMEM);
        s_init = 1;
    }

    float* ckv    = sym_addr(g_ckv);
    float* ckvT   = sym_addr(g_ckvT);
    float* krope  = sym_addr(g_krope);
    float* q      = sym_addr(g_q);
    float* qabs   = sym_addr(g_qabs);
    float* wukT   = sym_addr(g_wukT);
    float* scores = sym_addr(g_scores);
    float* ctxlat = sym_addr(g_ctxlat);
    float* ctx    = sym_addr(g_ctx);

    // 1) c_kv = rmsnorm(x @ W_DKV^T)  [tf32x3]
    run_gemm(x, W_DKV, ckv, ROWS, LL, DIN, DIN, DIN, LL,
             1, 1, 0, 0, 0, 0, 0, 0, 0, 3);
    rmsnorm_kernel<<<ROWS, 128>>>(ckv, kvw);
    {
        dim3 grid(LL / 32, SS / 32, BB), block(32, 8);
        transpose_kernel<<<grid, block>>>(ckv, ckvT, SS, LL,
                                          (long)SS * LL, (long)LL * SS);
    }

    // 2) k_rope = rope(x @ W_KRope^T)   [tf32]
    run_gemm(x, W_KRope, krope, ROWS, HH * RD, DIN, DIN, DIN, HH * RD,
             1, 1, 0, 0, 0, 0, 0, 0, 0, 1);
    {
        long total = (long)ROWS * HH * HALF_RD;
        rope_kernel<<<(int)((total + 255) / 256), 256>>>(krope, HH * RD, 0, offset);
    }

    // 3) q_total = x @ W_Q^T   [tf32]
    run_gemm(x, W_Q, q, ROWS, DOUT + HH * RD, DIN, DIN, DIN, DOUT + HH * RD,
             1, 1, 0, 0, 0, 0, 0, 0, 0, 1);
    {
        long total = (long)ROWS * HH * HALF_RD;
        rope_kernel<<<(int)((total + 255) / 256), 256>>>(q, DOUT + HH * RD, DOUT, offset);
    }

    // W_UK^T per head
    {
        dim3 grid(LL / 32, HD / 32, HH), block(32, 8);
        transpose_kernel<<<grid, block>>>(W_UK, wukT, HD, LL,
                                          (long)HD * LL, (long)LL * HD);
    }

    // 4) q_abs  [tf32]
    run_gemm(q, wukT, qabs, ROWS, LL, HD,
             DOUT + HH * RD, HD, HH * LL,
             HH, HH,
             0, HD, 0, (long)LL * HD, 0, LL, 0, 1);

    // 5a) scores = q_rope @ k_rope^T  (K=64)  [tf32]
    run_gemm(q + DOUT, krope, scores, SS, TT, RD,
             DOUT + HH * RD, HH * RD, TT,
             BB * HH, HH,
             (long)SS * (DOUT + HH * RD), RD,
             (long)SS * HH * RD, RD,
             (long)HH * SS * TT, (long)SS * TT, 0, 1);

    // 5b) scores += q_abs @ c_kv^T  (K=512)  [tf32]
    run_gemm(qabs, ckv, scores, SS, TT, LL,
             HH * LL, LL, TT,
             BB * HH, HH,
             (long)SS * HH * LL, LL,
             (long)SS * LL, 0,
             (long)HH * SS * TT, (long)SS * TT, 1, 1);

    // 6) masked scaled softmax (register-resident)
    softmax_kernel<<<BB * HH * SS, 256>>>(scores, offset);

    // 7) ctx_lat = attn @ c_kv (via ckvT)  [tf32 — attn>=0, error budget ok]
    run_gemm(scores, ckvT, ctxlat, SS, LL, TT,
             TT, SS, HH * LL,
             BB * HH, HH,
             (long)HH * SS * TT, (long)SS * TT,
             (long)LL * SS, 0,
             (long)SS * HH * LL, LL, 0, 1);

    // 8) ctx = ctx_lat @ W_UV^T per head  [tf32x3]
    run_gemm(ctxlat, W_UV, ctx, ROWS, HD, LL,
             HH * LL, LL, DOUT,
             HH, HH,
             0, LL, 0, (long)HD * LL, 0, HD, 0, 3);

    // 9) out = ctx @ W_O^T  [tf32x3]
    run_gemm(ctx, W_O, out, ROWS, DIN, DOUT,
             DOUT, DOUT, DIN,
             1, 1, 0, 0, 0, 0, 0, 0, 0, 3);
}

// round 5
// speedup vs baseline: 3.8105x; 1.3117x over previous
#include <cuda_runtime.h>
#include <cuda_bf16.h>
#include <math.h>
#include <stdint.h>

// Problem constants
#define BB 2
#define SS 2048
#define TT 2048
#define DIN 2048
#define DOUT 2048
#define HH 16
#define RD 64
#define HALF_RD 32
#define LL 512
#define HD 128
#define ROWS (BB*SS)          // 4096

// ---------------- device scratch (static; no allocations) ---------------------
__device__ __align__(128) float g_ckv  [BB*SS*LL];
__device__ __align__(128) float g_ckvT [BB*LL*SS];
__device__ __align__(128) float g_krope[BB*SS*HH*RD];
__device__ __align__(128) float g_q    [BB*SS*(DOUT+HH*RD)];
__device__ __align__(128) float g_qabs [ROWS*HH*LL];
__device__ __align__(128) float g_wukT [DOUT*LL];
__device__ __align__(128) float g_scores[(long)BB*HH*SS*TT];
__device__ __align__(128) float g_ctxlat[ROWS*HH*LL];
__device__ __align__(128) float g_ctx  [ROWS*DOUT];

// ================= helpers =====================================================
__device__ __forceinline__ float f2tf(float x) {
    uint32_t u; asm("cvt.rna.tf32.f32 %0, %1;" : "=r"(u) : "f"(x));
    return __uint_as_float(u);
}
__device__ __forceinline__ uint32_t smem_u32(const void* p) {
    uint32_t a;
    asm("{ .reg .u64 t; cvta.to.shared.u64 t, %1; cvt.u32.u64 %0, t; }" : "=r"(a) : "l"(p));
    return a;
}
__device__ __forceinline__ void cp16(uint32_t dst, const void* src) {
    asm volatile("cp.async.cg.shared.global [%0], [%1], 16;" :: "r"(dst), "l"(src));
}
#define CP_COMMIT() asm volatile("cp.async.commit_group;" ::: "memory")
#define CP_WAIT2()  asm volatile("cp.async.wait_group 2;"  ::: "memory")

__device__ __forceinline__ void ldsm4(uint32_t* r, uint32_t addr) {
    asm volatile("ldmatrix.sync.aligned.m8n8.x4.shared.b16 {%0,%1,%2,%3}, [%4];"
                 : "=r"(r[0]), "=r"(r[1]), "=r"(r[2]), "=r"(r[3]) : "r"(addr));
}

__device__ __forceinline__ void mma_tf32(float* c, const uint32_t* a, const uint32_t* b) {
    asm volatile(
        "mma.sync.aligned.m16n8k8.row.col.f32.tf32.tf32.f32 "
        "{%0,%1,%2,%3}, {%4,%5,%6,%7}, {%8,%9}, {%0,%1,%2,%3};"
        : "+f"(c[0]), "+f"(c[1]), "+f"(c[2]), "+f"(c[3])
        : "r"(a[0]), "r"(a[1]), "r"(a[2]), "r"(a[3]), "r"(b[0]), "r"(b[1]));
}

// ================= GEMM body (cp.async pipeline + ldmatrix) ====================
// C[m0..+128, n0..+128] (+)= A[m0..+128, :K] @ B[n0..+128, :K]^T
// A lda, B ldb row-major K-contiguous. K % 16 == 0, K >= 64.
#define STAGEF 5120                 // floats per stage (2560 A + 2560 B)
#define GEMM_SMEM (4*STAGEF*4)      // 81920 bytes

template<int PREC>
__device__ __forceinline__ void gemm_body(
    const float* __restrict__ A, const float* __restrict__ B, float* __restrict__ C,
    int K, int lda, int ldb, int ldc, int m0, int n0, int accumulate, float* sm)
{
    const int tid  = threadIdx.x;
    const int lane = tid & 31;
    const int wid  = tid >> 5;
    const int gid  = lane >> 2;
    const int tig  = lane & 3;
    const int wm   = wid >> 2;   // 0..1
    const int wn   = wid & 3;    // 0..3

    A += (long)m0 * lda;
    B += (long)n0 * ldb;

    const uint32_t sbase = smem_u32(sm);

    // ldmatrix per-thread base offsets (bytes within a 128x16 pad-20 tile)
    const int r8   = lane & 7;
    const int aRow = wm * 64 + r8 + ((lane >> 3) & 1) * 8;   // + mt*16
    const int aCol = ((lane >> 4) & 1) * 4;                  // + ks*8
    const uint32_t aOff = (uint32_t)(aRow * 20 + aCol) * 4;
    const int bRow = wn * 32 + r8 + ((lane >> 4) & 1) * 8;   // + ntp*16
    const int bCol = ((lane >> 3) & 1) * 4;                  // + ks*8
    const uint32_t bOff = (uint32_t)(bRow * 20 + bCol) * 4;

    float acc[4][4][4];
    #pragma unroll
    for (int mt = 0; mt < 4; mt++)
        #pragma unroll
        for (int nt = 0; nt < 4; nt++)
            #pragma unroll
            for (int i = 0; i < 4; i++) acc[mt][nt][i] = 0.0f;

    const int crow = tid >> 2;          // 0..63
    const int cc4  = tid & 3;           // 0..3
    auto issue = [&](int c) {
        const int k0  = c << 4;
        const uint32_t st = sbase + (uint32_t)(c & 3) * (STAGEF * 4);
        #pragma unroll
        for (int i = 0; i < 2; i++) {
            int row = crow + i * 64;
            uint32_t d = st + (uint32_t)(row * 20 + cc4 * 4) * 4;
            cp16(d,             A + (long)row * lda + k0 + cc4 * 4);
            cp16(d + 2560 * 4,  B + (long)row * ldb + k0 + cc4 * 4);
        }
    };

    auto compute = [&](int c) {
        const uint32_t As = sbase + (uint32_t)(c & 3) * (STAGEF * 4);
        const uint32_t Bs = As + 2560 * 4;
        #pragma unroll
        for (int ks = 0; ks < 2; ks++) {
            uint32_t ah[4][4], bh[4][2];
            uint32_t al[4][4], bl[4][2];
            #pragma unroll
            for (int mt = 0; mt < 4; mt++) {
                uint32_t raw[4];
                ldsm4(raw, As + aOff + (uint32_t)(mt * 16 * 20 + ks * 8) * 4);
                #pragma unroll
                for (int i = 0; i < 4; i++) {
                    float v = __uint_as_float(raw[i]);
                    float h = f2tf(v);
                    ah[mt][i] = __float_as_uint(h);
                    if (PREC == 3) al[mt][i] = __float_as_uint(f2tf(v - h));
                }
            }
            #pragma unroll
            for (int ntp = 0; ntp < 2; ntp++) {
                uint32_t raw[4];
                ldsm4(raw, Bs + bOff + (uint32_t)(ntp * 16 * 20 + ks * 8) * 4);
                #pragma unroll
                for (int i = 0; i < 4; i++) {
                    float v = __uint_as_float(raw[i]);
                    float h = f2tf(v);
                    int nt = ntp * 2 + (i >> 1), kk = i & 1;
                    bh[nt][kk] = __float_as_uint(h);
                    if (PREC == 3) bl[nt][kk] = __float_as_uint(f2tf(v - h));
                }
            }
            #pragma unroll
            for (int mt = 0; mt < 4; mt++)
                #pragma unroll
                for (int nt = 0; nt < 4; nt++)
                    mma_tf32(acc[mt][nt], ah[mt], bh[nt]);
            if (PREC == 3) {
                #pragma unroll
                for (int mt = 0; mt < 4; mt++)
                    #pragma unroll
                    for (int nt = 0; nt < 4; nt++) {
                        mma_tf32(acc[mt][nt], ah[mt], bl[nt]);
                        mma_tf32(acc[mt][nt], al[mt], bh[nt]);
                    }
            }
        }
    };

    const int NC = K >> 4;
    issue(0); CP_COMMIT();
    issue(1); CP_COMMIT();
    issue(2); CP_COMMIT();
    for (int c = 0; c < NC; c++) {
        CP_WAIT2();
        __syncthreads();
        if (c + 3 < NC) issue(c + 3);
        CP_COMMIT();
        compute(c);
    }

    #pragma unroll
    for (int mt = 0; mt < 4; mt++) {
        #pragma unroll
        for (int nt = 0; nt < 4; nt++) {
            int r  = m0 + wm * 64 + mt * 16 + gid;
            int cc = n0 + wn * 32 + nt * 8 + tig * 2;
            float2* p0 = (float2*)&C[(long)r * ldc + cc];
            float2* p1 = (float2*)&C[(long)(r + 8) * ldc + cc];
            float2 v0 = { acc[mt][nt][0], acc[mt][nt][1] };
            float2 v1 = { acc[mt][nt][2], acc[mt][nt][3] };
            if (accumulate) {
                float2 o0 = *p0, o1 = *p1;
                v0.x += o0.x; v0.y += o0.y;
                v1.x += o1.x; v1.y += o1.y;
            }
            *p0 = v0;
            *p1 = v1;
        }
    }
}

template<int PREC, int MINCTA>
__global__ void __launch_bounds__(256, MINCTA)
gemm_cp(const float* __restrict__ Ab, const float* __restrict__ Bb, float* __restrict__ Cb,
        int K, int lda, int ldb, int ldc,
        int zInner, long sAo, long sAi, long sBo, long sBi, long sCo, long sCi,
        int accumulate)
{
    extern __shared__ float sm[];
    const int z  = blockIdx.z;
    const int zo = z / zInner, zi = z % zInner;
    gemm_body<PREC>(Ab + zo * sAo + zi * sAi, Bb + zo * sBo + zi * sBi,
                    Cb + zo * sCo + zi * sCi,
                    K, lda, ldb, ldc, blockIdx.y * 128, blockIdx.x * 128,
                    accumulate, sm);
}

// fused triple projection: seg by blockIdx.x (4 | 8 | 24 blocks along N)
__global__ void __launch_bounds__(256, 2)
gemm_proj3(const float* __restrict__ x,
           const float* __restrict__ Wdkv, const float* __restrict__ Wkr,
           const float* __restrict__ Wq,
           float* __restrict__ ckv, float* __restrict__ krope, float* __restrict__ q)
{
    extern __shared__ float sm[];
    const int bx = blockIdx.x;
    const float* B; float* C; int ldc, n0;
    if (bx < 4)       { B = Wdkv; C = ckv;   ldc = LL;            n0 = bx * 128; }
    else if (bx < 12) { B = Wkr;  C = krope; ldc = HH * RD;       n0 = (bx - 4) * 128; }
    else              { B = Wq;   C = q;     ldc = DOUT + HH * RD; n0 = (bx - 12) * 128; }
    gemm_body<1>(x, B, C, DIN, DIN, DIN, ldc, blockIdx.y * 128, n0, 0, sm);
}

// ================= small kernels ===============================================
__global__ void rmsnorm_kernel(float* __restrict__ data, const float* __restrict__ w)
{
    const int row = blockIdx.x;
    float* p = data + (long)row * LL;
    float ss = 0.0f;
    for (int i = threadIdx.x; i < LL; i += blockDim.x) { float v = p[i]; ss += v * v; }
    __shared__ float red[32];
    for (int o = 16; o; o >>= 1) ss += __shfl_xor_sync(0xffffffffu, ss, o);
    if ((threadIdx.x & 31) == 0) red[threadIdx.x >> 5] = ss;
    __syncthreads();
    if (threadIdx.x < 32) {
        float v = (threadIdx.x < (blockDim.x >> 5)) ? red[threadIdx.x] : 0.0f;
        for (int o = 16; o; o >>= 1) v += __shfl_xor_sync(0xffffffffu, v, o);
        if (threadIdx.x == 0) red[0] = v;
    }
    __syncthreads();
    float rstd = rsqrtf(red[0] / (float)LL + 1e-6f);
    for (int i = threadIdx.x; i < LL; i += blockDim.x) p[i] = p[i] * rstd * w[i];
}

__global__ void rope_kernel(float* __restrict__ data, int ld, int colbase,
                            const int* __restrict__ offset_p)
{
    long idx = (long)blockIdx.x * blockDim.x + threadIdx.x;
    const long total = (long)ROWS * HH * HALF_RD;
    if (idx >= total) return;
    int  j   = (int)(idx % HALF_RD);
    int  h   = (int)((idx / HALF_RD) % HH);
    long row = idx / (HALF_RD * HH);
    int  s   = (int)(row % SS);
    float pos = (float)(s + *offset_p);
    float inv = expf(-(float)j * (logf(10000.0f) / 32.0f));
    float ang = pos * inv;
    float c  = cosf(ang);
    float si = sinf(ang);
    float* p = data + row * (long)ld + colbase + h * RD;
    float x1 = p[j], x2 = p[j + HALF_RD];
    p[j]           = x1 * c - x2 * si;
    p[j + HALF_RD] = x2 * c + x1 * si;
}

// register-resident masked scaled softmax; 256 threads, 8 els/thread (T=2048)
__global__ void __launch_bounds__(256)
softmax_kernel(float* __restrict__ scores, const int* __restrict__ offset_p)
{
    const long row = blockIdx.x;            // (b*H+h)*S + s
    const int  s   = (int)(row % SS);
    int valid = s + *offset_p + 1;
    if (valid > TT) valid = TT;
    float* p = scores + row * (long)TT;
    const float scale = rsqrtf((float)(HD + RD));
    const int tid = threadIdx.x;

    float4 v[2];
    float m = -INFINITY;
    #pragma unroll
    for (int i = 0; i < 2; i++) {
        int e0 = (tid + i * 256) * 4;
        v[i] = *(const float4*)(p + e0);
        float* f = (float*)&v[i];
        #pragma unroll
        for (int j = 0; j < 4; j++) {
            f[j] = (e0 + j < valid) ? f[j] * scale : -INFINITY;
            m = fmaxf(m, f[j]);
        }
    }
    __shared__ float red[32];
    for (int o = 16; o; o >>= 1) m = fmaxf(m, __shfl_xor_sync(0xffffffffu, m, o));
    if ((tid & 31) == 0) red[tid >> 5] = m;
    __syncthreads();
    if (tid < 32) {
        float t = (tid < 8) ? red[tid] : -INFINITY;
        for (int o = 16; o; o >>= 1) t = fmaxf(t, __shfl_xor_sync(0xffffffffu, t, o));
        if (tid == 0) red[0] = t;
    }
    __syncthreads();
    m = red[0];
    __syncthreads();

    float sum = 0.0f;
    #pragma unroll
    for (int i = 0; i < 2; i++) {
        float* f = (float*)&v[i];
        #pragma unroll
        for (int j = 0; j < 4; j++) {
            float e = (f[j] == -INFINITY) ? 0.0f : expf(f[j] - m);
            f[j] = e;
            sum += e;
        }
    }
    for (int o = 16; o; o >>= 1) sum += __shfl_xor_sync(0xffffffffu, sum, o);
    if ((tid & 31) == 0) red[tid >> 5] = sum;
    __syncthreads();
    if (tid < 32) {
        float t = (tid < 8) ? red[tid] : 0.0f;
        for (int o = 16; o; o >>= 1) t += __shfl_xor_sync(0xffffffffu, t, o);
        if (tid == 0) red[0] = t;
    }
    __syncthreads();
    float inv = 1.0f / red[0];
    #pragma unroll
    for (int i = 0; i < 2; i++) {
        float* f = (float*)&v[i];
        #pragma unroll
        for (int j = 0; j < 4; j++) f[j] *= inv;
        *(float4*)(p + (tid + i * 256) * 4) = v[i];
    }
}

// 32x32 tiled transpose: out[c, r] = in[r, c], batched over z
__global__ void transpose_kernel(const float* __restrict__ in, float* __restrict__ out,
                                 int R, int Cc, long sIn, long sOut)
{
    __shared__ float t[32][33];
    const float* ip = in + blockIdx.z * sIn;
    float* op = out + blockIdx.z * sOut;
    const int c0 = blockIdx.x * 32, r0 = blockIdx.y * 32;
    for (int i = threadIdx.y; i < 32; i += 8)
        t[i][threadIdx.x] = ip[(long)(r0 + i) * Cc + c0 + threadIdx.x];
    __syncthreads();
    for (int i = threadIdx.y; i < 32; i += 8)
        op[(long)(c0 + i) * R + r0 + threadIdx.x] = t[threadIdx.x][i];
}

// ================= host side ====================================================
static float* sym_addr(const void* sym)
{
    void* p = nullptr;
    cudaGetSymbolAddress(&p, sym);
    return (float*)p;
}

static void run_gemm(const float* A, const float* B, float* C,
                     int M, int N, int K, int lda, int ldb, int ldc,
                     int Z, int zInner,
                     long sAo, long sAi, long sBo, long sBi, long sCo, long sCi,
                     int accumulate, int prec)
{
    dim3 grid(N / 128, M / 128, Z);
    if (prec == 3)
        gemm_cp<3,1><<<grid, 256, GEMM_SMEM>>>(A, B, C, K, lda, ldb, ldc,
                                               zInner, sAo, sAi, sBo, sBi, sCo, sCi, accumulate);
    else
        gemm_cp<1,2><<<grid, 256, GEMM_SMEM>>>(A, B, C, K, lda, ldb, ldc,
                                               zInner, sAo, sAi, sBo, sBi, sCo, sCi, accumulate);
}

extern "C" void kernel_launch(void* const* d_in, const int* in_sizes, int n_in,
                              void* d_out, int out_size)
{
    const float* x       = (const float*)d_in[0];
    const float* W_DKV   = (const float*)d_in[1];
    const float* W_KRope = (const float*)d_in[2];
    const float* W_Q     = (const float*)d_in[3];
    const float* W_UK    = (const float*)d_in[4];
    const float* W_UV    = (const float*)d_in[5];
    const float* W_O     = (const float*)d_in[6];
    const float* kvw     = (const float*)d_in[7];
    const int*   offset  = (const int*)d_in[8];
    float* out = (float*)d_out;

    static int s_init = 0;
    if (!s_init) {
        cudaFuncSetAttribute((const void*)gemm_cp<1,2>, cudaFuncAttributeMaxDynamicSharedMemorySize, GEMM_SMEM);
        cudaFuncSetAttribute((const void*)gemm_cp<3,1>, cudaFuncAttributeMaxDynamicSharedMemorySize, GEMM_SMEM);
        cudaFuncSetAttribute((const void*)gemm_proj3, cudaFuncAttributeMaxDynamicSharedMemorySize, GEMM_SMEM);
        s_init = 1;
    }

    float* ckv    = sym_addr(g_ckv);
    float* ckvT   = sym_addr(g_ckvT);
    float* krope  = sym_addr(g_krope);
    float* q      = sym_addr(g_q);
    float* qabs   = sym_addr(g_qabs);
    float* wukT   = sym_addr(g_wukT);
    float* scores = sym_addr(g_scores);
    float* ctxlat = sym_addr(g_ctxlat);
    float* ctx    = sym_addr(g_ctx);

    // 1-3) fused projections: ckv raw, krope raw, q   [tf32]
    {
        dim3 grid(36, 32, 1);
        gemm_proj3<<<grid, 256, GEMM_SMEM>>>(x, W_DKV, W_KRope, W_Q, ckv, krope, q);
    }
    rmsnorm_kernel<<<ROWS, 128>>>(ckv, kvw);
    {
        dim3 grid(LL / 32, SS / 32, BB), block(32, 8);
        transpose_kernel<<<grid, block>>>(ckv, ckvT, SS, LL,
                                          (long)SS * LL, (long)LL * SS);
    }
    {
        long total = (long)ROWS * HH * HALF_RD;
        rope_kernel<<<(int)((total + 255) / 256), 256>>>(krope, HH * RD, 0, offset);
        rope_kernel<<<(int)((total + 255) / 256), 256>>>(q, DOUT + HH * RD, DOUT, offset);
    }

    // W_UK^T per head
    {
        dim3 grid(LL / 32, HD / 32, HH), block(32, 8);
        transpose_kernel<<<grid, block>>>(W_UK, wukT, HD, LL,
                                          (long)HD * LL, (long)LL * HD);
    }

    // 4) q_abs  [tf32]
    run_gemm(q, wukT, qabs, ROWS, LL, HD,
             DOUT + HH * RD, HD, HH * LL,
             HH, HH,
             0, HD, 0, (long)LL * HD, 0, LL, 0, 1);

    // 5a) scores = q_rope @ k_rope^T  (K=64)  [tf32]
    run_gemm(q + DOUT, krope, scores, SS, TT, RD,
             DOUT + HH * RD, HH * RD, TT,
             BB * HH, HH,
             (long)SS * (DOUT + HH * RD), RD,
             (long)SS * HH * RD, RD,
             (long)HH * SS * TT, (long)SS * TT, 0, 1);

    // 5b) scores += q_abs @ c_kv^T  (K=512)  [tf32]
    run_gemm(qabs, ckv, scores, SS, TT, LL,
             HH * LL, LL, TT,
             BB * HH, HH,
             (long)SS * HH * LL, LL,
             (long)SS * LL, 0,
             (long)HH * SS * TT, (long)SS * TT, 1, 1);

    // 6) masked scaled softmax (register-resident)
    softmax_kernel<<<BB * HH * SS, 256>>>(scores, offset);

    // 7) ctx_lat = attn @ c_kv (via ckvT)  [tf32]
    run_gemm(scores, ckvT, ctxlat, SS, LL, TT,
             TT, SS, HH * LL,
             BB * HH, HH,
             (long)HH * SS * TT, (long)SS * TT,
             (long)LL * SS, 0,
             (long)SS * HH * LL, LL, 0, 1);

    // 8) ctx = ctx_lat @ W_UV^T per head  [tf32x3]
    run_gemm(ctxlat, W_UV, ctx, ROWS, HD, LL,
             HH * LL, LL, DOUT,
             HH, HH,
             0, LL, 0, (long)HD * LL, 0, HD, 0, 3);

    // 9) out = ctx @ W_O^T  [tf32]
    run_gemm(ctx, W_O, out, ROWS, DIN, DOUT,
             DOUT, DOUT, DIN,
             1, 1, 0, 0, 0, 0, 0, 0, 0, 1);
}

// round 6
// speedup vs baseline: 5.4013x; 1.4175x over previous
#include <cuda_runtime.h>
#include <cuda_bf16.h>
#include <math.h>
#include <stdint.h>

// Problem constants
#define BB 2
#define SS 2048
#define TT 2048
#define DIN 2048
#define DOUT 2048
#define HH 16
#define RD 64
#define HALF_RD 32
#define LL 512
#define HD 128
#define ROWS (BB*SS)          // 4096

// ---------------- device scratch (static; no allocations) ---------------------
__device__ __align__(128) float g_ckv  [BB*SS*LL];
__device__ __align__(128) float g_ckvT [BB*LL*SS];
__device__ __align__(128) float g_krope[BB*SS*HH*RD];
__device__ __align__(128) float g_q    [BB*SS*(DOUT+HH*RD)];
__device__ __align__(128) float g_qabs [ROWS*HH*LL];
__device__ __align__(128) float g_wukT [DOUT*LL];
__device__ __align__(128) float g_scores[(long)BB*HH*SS*TT];
__device__ __align__(128) float g_ctxlat[ROWS*HH*LL];
__device__ __align__(128) float g_ctx  [ROWS*DOUT];

// ================= helpers =====================================================
__device__ __forceinline__ float f2tf(float x) {
    uint32_t u; asm("cvt.rna.tf32.f32 %0, %1;" : "=r"(u) : "f"(x));
    return __uint_as_float(u);
}
__device__ __forceinline__ uint32_t smem_u32(const void* p) {
    uint32_t a;
    asm("{ .reg .u64 t; cvta.to.shared.u64 t, %1; cvt.u32.u64 %0, t; }" : "=r"(a) : "l"(p));
    return a;
}
__device__ __forceinline__ void cp16(uint32_t dst, const void* src) {
    asm volatile("cp.async.cg.shared.global [%0], [%1], 16;" :: "r"(dst), "l"(src));
}
#define CP_COMMIT() asm volatile("cp.async.commit_group;" ::: "memory")
#define CP_WAIT2()  asm volatile("cp.async.wait_group 2;"  ::: "memory")
#define CP_WAIT0()  asm volatile("cp.async.wait_group 0;"  ::: "memory")

__device__ __forceinline__ void ldsm4(uint32_t* r, uint32_t addr) {
    asm volatile("ldmatrix.sync.aligned.m8n8.x4.shared.b16 {%0,%1,%2,%3}, [%4];"
                 : "=r"(r[0]), "=r"(r[1]), "=r"(r[2]), "=r"(r[3]) : "r"(addr));
}

__device__ __forceinline__ void mma_tf32(float* c, const uint32_t* a, const uint32_t* b) {
    asm volatile(
        "mma.sync.aligned.m16n8k8.row.col.f32.tf32.tf32.f32 "
        "{%0,%1,%2,%3}, {%4,%5,%6,%7}, {%8,%9}, {%0,%1,%2,%3};"
        : "+f"(c[0]), "+f"(c[1]), "+f"(c[2]), "+f"(c[3])
        : "r"(a[0]), "r"(a[1]), "r"(a[2]), "r"(a[3]), "r"(b[0]), "r"(b[1]));
}

// ================= GEMM tile engine (cp.async + ldmatrix) ======================
// acc += A[0..128, :K] @ B[0..128, :K]^T ; caller pre-offsets A,B to tile origin.
// K % 16 == 0, K >= 64.
#define STAGEF 5120                 // floats per stage (2560 A + 2560 B)
#define GEMM_SMEM (4*STAGEF*4)      // 81920 bytes

template<int PREC>
__device__ __forceinline__ void gemm_tiles(
    const float* __restrict__ A, const float* __restrict__ B,
    int K, int lda, int ldb, float (*acc)[4][4], float* sm)
{
    const int tid  = threadIdx.x;
    const int lane = tid & 31;
    const int wid  = tid >> 5;
    const int wm   = wid >> 2;   // 0..1
    const int wn   = wid & 3;    // 0..3

    const uint32_t sbase = smem_u32(sm);

    const int r8   = lane & 7;
    const int aRow = wm * 64 + r8 + ((lane >> 3) & 1) * 8;
    const int aCol = ((lane >> 4) & 1) * 4;
    const uint32_t aOff = (uint32_t)(aRow * 20 + aCol) * 4;
    const int bRow = wn * 32 + r8 + ((lane >> 4) & 1) * 8;
    const int bCol = ((lane >> 3) & 1) * 4;
    const uint32_t bOff = (uint32_t)(bRow * 20 + bCol) * 4;

    const int crow = tid >> 2;          // 0..63
    const int cc4  = tid & 3;           // 0..3
    auto issue = [&](int c) {
        const int k0  = c << 4;
        const uint32_t st = sbase + (uint32_t)(c & 3) * (STAGEF * 4);
        #pragma unroll
        for (int i = 0; i < 2; i++) {
            int row = crow + i * 64;
            uint32_t d = st + (uint32_t)(row * 20 + cc4 * 4) * 4;
            cp16(d,             A + (long)row * lda + k0 + cc4 * 4);
            cp16(d + 2560 * 4,  B + (long)row * ldb + k0 + cc4 * 4);
        }
    };

    auto compute = [&](int c) {
        const uint32_t As = sbase + (uint32_t)(c & 3) * (STAGEF * 4);
        const uint32_t Bs = As + 2560 * 4;
        #pragma unroll
        for (int ks = 0; ks < 2; ks++) {
            uint32_t ah[4][4], bh[4][2];
            uint32_t al[4][4], bl[4][2];
            #pragma unroll
            for (int mt = 0; mt < 4; mt++) {
                uint32_t raw[4];
                ldsm4(raw, As + aOff + (uint32_t)(mt * 16 * 20 + ks * 8) * 4);
                #pragma unroll
                for (int i = 0; i < 4; i++) {
                    float v = __uint_as_float(raw[i]);
                    float h = f2tf(v);
                    ah[mt][i] = __float_as_uint(h);
                    if (PREC == 3) al[mt][i] = __float_as_uint(f2tf(v - h));
                }
            }
            #pragma unroll
            for (int ntp = 0; ntp < 2; ntp++) {
                uint32_t raw[4];
                ldsm4(raw, Bs + bOff + (uint32_t)(ntp * 16 * 20 + ks * 8) * 4);
                #pragma unroll
                for (int i = 0; i < 4; i++) {
                    float v = __uint_as_float(raw[i]);
                    float h = f2tf(v);
                    int nt = ntp * 2 + (i >> 1), kk = i & 1;
                    bh[nt][kk] = __float_as_uint(h);
                    if (PREC == 3) bl[nt][kk] = __float_as_uint(f2tf(v - h));
                }
            }
            #pragma unroll
            for (int mt = 0; mt < 4; mt++)
                #pragma unroll
                for (int nt = 0; nt < 4; nt++)
                    mma_tf32(acc[mt][nt], ah[mt], bh[nt]);
            if (PREC == 3) {
                #pragma unroll
                for (int mt = 0; mt < 4; mt++)
                    #pragma unroll
                    for (int nt = 0; nt < 4; nt++) {
                        mma_tf32(acc[mt][nt], ah[mt], bl[nt]);
                        mma_tf32(acc[mt][nt], al[mt], bh[nt]);
                    }
            }
        }
    };

    const int NC = K >> 4;
    issue(0); CP_COMMIT();
    issue(1); CP_COMMIT();
    issue(2); CP_COMMIT();
    for (int c = 0; c < NC; c++) {
        CP_WAIT2();
        __syncthreads();
        if (c + 3 < NC) issue(c + 3);
        CP_COMMIT();
        compute(c);
    }
    CP_WAIT0();
    __syncthreads();
}

__device__ __forceinline__ void gemm_epilogue(
    float* __restrict__ C, int ldc, int m0, int n0,
    float (*acc)[4][4], int accumulate)
{
    const int lane = threadIdx.x & 31;
    const int wid  = threadIdx.x >> 5;
    const int gid  = lane >> 2;
    const int tig  = lane & 3;
    const int wm   = wid >> 2;
    const int wn   = wid & 3;
    #pragma unroll
    for (int mt = 0; mt < 4; mt++) {
        #pragma unroll
        for (int nt = 0; nt < 4; nt++) {
            int r  = m0 + wm * 64 + mt * 16 + gid;
            int cc = n0 + wn * 32 + nt * 8 + tig * 2;
            float2* p0 = (float2*)&C[(long)r * ldc + cc];
            float2* p1 = (float2*)&C[(long)(r + 8) * ldc + cc];
            float2 v0 = { acc[mt][nt][0], acc[mt][nt][1] };
            float2 v1 = { acc[mt][nt][2], acc[mt][nt][3] };
            if (accumulate) {
                float2 o0 = *p0, o1 = *p1;
                v0.x += o0.x; v0.y += o0.y;
                v1.x += o1.x; v1.y += o1.y;
            }
            *p0 = v0;
            *p1 = v1;
        }
    }
}

// generic batched GEMM; kclip=1 limits K to round128(m0+128+*offset_p) (causal)
template<int PREC, int MINCTA>
__global__ void __launch_bounds__(256, MINCTA)
gemm_cp(const float* __restrict__ Ab, const float* __restrict__ Bb, float* __restrict__ Cb,
        int K, int lda, int ldb, int ldc,
        int zInner, long sAo, long sAi, long sBo, long sBi, long sCo, long sCi,
        int accumulate, const int* offset_p, int kclip)
{
    extern __shared__ float sm[];
    const int z  = blockIdx.z;
    const int zo = z / zInner, zi = z % zInner;
    const int m0 = blockIdx.y * 128;
    const int n0 = blockIdx.x * 128;
    if (kclip) {
        int lim = m0 + 128 + *offset_p;
        lim = (lim + 127) & ~127;
        if (lim < K) K = lim;
    }
    float acc[4][4][4];
    #pragma unroll
    for (int mt = 0; mt < 4; mt++)
        #pragma unroll
        for (int nt = 0; nt < 4; nt++)
            #pragma unroll
            for (int i = 0; i < 4; i++) acc[mt][nt][i] = 0.0f;
    gemm_tiles<PREC>(Ab + zo * sAo + zi * sAi + (long)m0 * lda,
                     Bb + zo * sBo + zi * sBi + (long)n0 * ldb,
                     K, lda, ldb, acc, sm);
    gemm_epilogue(Cb + zo * sCo + zi * sCi, ldc, m0, n0, acc, accumulate);
}

// fused triple projection: seg by blockIdx.x (4 | 8 | 24 blocks along N)
__global__ void __launch_bounds__(256, 2)
gemm_proj3(const float* __restrict__ x,
           const float* __restrict__ Wdkv, const float* __restrict__ Wkr,
           const float* __restrict__ Wq,
           float* __restrict__ ckv, float* __restrict__ krope, float* __restrict__ q)
{
    extern __shared__ float sm[];
    const int bx = blockIdx.x;
    const float* B; float* C; int ldc, n0;
    if (bx < 4)       { B = Wdkv; C = ckv;   ldc = LL;             n0 = bx * 128; }
    else if (bx < 12) { B = Wkr;  C = krope; ldc = HH * RD;        n0 = (bx - 4) * 128; }
    else              { B = Wq;   C = q;     ldc = DOUT + HH * RD; n0 = (bx - 12) * 128; }
    const int m0 = blockIdx.y * 128;
    float acc[4][4][4];
    #pragma unroll
    for (int mt = 0; mt < 4; mt++)
        #pragma unroll
        for (int nt = 0; nt < 4; nt++)
            #pragma unroll
            for (int i = 0; i < 4; i++) acc[mt][nt][i] = 0.0f;
    gemm_tiles<1>(x + (long)m0 * DIN, B + (long)n0 * DIN, DIN, DIN, DIN, acc, sm);
    gemm_epilogue(C, ldc, m0, n0, acc, 0);
}

// fused scores: rope part (K=64) + latent part (K=512), causal block skip
__global__ void __launch_bounds__(256, 2)
gemm_scores(const float* __restrict__ q, const float* __restrict__ krope,
            const float* __restrict__ qabs, const float* __restrict__ ckv,
            float* __restrict__ scores, const int* __restrict__ offset_p)
{
    extern __shared__ float sm[];
    const int m0 = blockIdx.y * 128;
    const int n0 = blockIdx.x * 128;
    if (n0 > m0 + 127 + *offset_p) return;      // fully masked, never read
    const int b = blockIdx.z >> 4;
    const int h = blockIdx.z & 15;

    float acc[4][4][4];
    #pragma unroll
    for (int mt = 0; mt < 4; mt++)
        #pragma unroll
        for (int nt = 0; nt < 4; nt++)
            #pragma unroll
            for (int i = 0; i < 4; i++) acc[mt][nt][i] = 0.0f;

    const float* A1 = q + (long)b * SS * (DOUT + HH * RD) + DOUT + h * RD
                        + (long)m0 * (DOUT + HH * RD);
    const float* B1 = krope + (long)b * SS * (HH * RD) + h * RD + (long)n0 * (HH * RD);
    gemm_tiles<1>(A1, B1, RD, DOUT + HH * RD, HH * RD, acc, sm);

    const float* A2 = qabs + (long)b * SS * (HH * LL) + h * LL + (long)m0 * (HH * LL);
    const float* B2 = ckv + (long)b * SS * LL + (long)n0 * LL;
    gemm_tiles<1>(A2, B2, LL, HH * LL, LL, acc, sm);

    gemm_epilogue(scores + (long)blockIdx.z * SS * TT, TT, m0, n0, acc, 0);
}

// ================= small kernels ===============================================
__global__ void rmsnorm_kernel(float* __restrict__ data, const float* __restrict__ w)
{
    const int row = blockIdx.x;
    float* p = data + (long)row * LL;
    float ss = 0.0f;
    for (int i = threadIdx.x; i < LL; i += blockDim.x) { float v = p[i]; ss += v * v; }
    __shared__ float red[32];
    for (int o = 16; o; o >>= 1) ss += __shfl_xor_sync(0xffffffffu, ss, o);
    if ((threadIdx.x & 31) == 0) red[threadIdx.x >> 5] = ss;
    __syncthreads();
    if (threadIdx.x < 32) {
        float v = (threadIdx.x < (blockDim.x >> 5)) ? red[threadIdx.x] : 0.0f;
        for (int o = 16; o; o >>= 1) v += __shfl_xor_sync(0xffffffffu, v, o);
        if (threadIdx.x == 0) red[0] = v;
    }
    __syncthreads();
    float rstd = rsqrtf(red[0] / (float)LL + 1e-6f);
    for (int i = threadIdx.x; i < LL; i += blockDim.x) p[i] = p[i] * rstd * w[i];
}

__global__ void rope_kernel(float* __restrict__ data, int ld, int colbase,
                            const int* __restrict__ offset_p)
{
    long idx = (long)blockIdx.x * blockDim.x + threadIdx.x;
    const long total = (long)ROWS * HH * HALF_RD;
    if (idx >= total) return;
    int  j   = (int)(idx % HALF_RD);
    int  h   = (int)((idx / HALF_RD) % HH);
    long row = idx / (HALF_RD * HH);
    int  s   = (int)(row % SS);
    float pos = (float)(s + *offset_p);
    float inv = expf(-(float)j * (logf(10000.0f) / 32.0f));
    float ang = pos * inv;
    float c  = cosf(ang);
    float si = sinf(ang);
    float* p = data + row * (long)ld + colbase + h * RD;
    float x1 = p[j], x2 = p[j + HALF_RD];
    p[j]           = x1 * c - x2 * si;
    p[j + HALF_RD] = x2 * c + x1 * si;
}

// masked scaled softmax; loads only valid part, writes only up to 128-block limit
__global__ void __launch_bounds__(256)
softmax_kernel(float* __restrict__ scores, const int* __restrict__ offset_p)
{
    const long row = blockIdx.x;            // (b*H+h)*S + s
    const int  s   = (int)(row % SS);
    const int  off = *offset_p;
    int valid = s + off + 1;
    if (valid > TT) valid = TT;
    int limit = ((s & ~127) + 128 + off + 127) & ~127;
    if (limit > TT) limit = TT;
    float* p = scores + row * (long)TT;
    const float scale = rsqrtf((float)(HD + RD));
    const int tid = threadIdx.x;

    float4 v[2];
    float m = -INFINITY;
    #pragma unroll
    for (int i = 0; i < 2; i++) {
        int e0 = (tid + i * 256) * 4;
        float* f = (float*)&v[i];
        if (e0 < valid) {
            v[i] = *(const float4*)(p + e0);
            #pragma unroll
            for (int j = 0; j < 4; j++) {
                f[j] = (e0 + j < valid) ? f[j] * scale : -INFINITY;
                m = fmaxf(m, f[j]);
            }
        } else {
            f[0] = f[1] = f[2] = f[3] = -INFINITY;
        }
    }
    __shared__ float red[32];
    for (int o = 16; o; o >>= 1) m = fmaxf(m, __shfl_xor_sync(0xffffffffu, m, o));
    if ((tid & 31) == 0) red[tid >> 5] = m;
    __syncthreads();
    if (tid < 32) {
        float t = (tid < 8) ? red[tid] : -INFINITY;
        for (int o = 16; o; o >>= 1) t = fmaxf(t, __shfl_xor_sync(0xffffffffu, t, o));
        if (tid == 0) red[0] = t;
    }
    __syncthreads();
    m = red[0];
    __syncthreads();

    float sum = 0.0f;
    #pragma unroll
    for (int i = 0; i < 2; i++) {
        float* f = (float*)&v[i];
        #pragma unroll
        for (int j = 0; j < 4; j++) {
            float e = (f[j] == -INFINITY) ? 0.0f : expf(f[j] - m);
            f[j] = e;
            sum += e;
        }
    }
    for (int o = 16; o; o >>= 1) sum += __shfl_xor_sync(0xffffffffu, sum, o);
    if ((tid & 31) == 0) red[tid >> 5] = sum;
    __syncthreads();
    if (tid < 32) {
        float t = (tid < 8) ? red[tid] : 0.0f;
        for (int o = 16; o; o >>= 1) t += __shfl_xor_sync(0xffffffffu, t, o);
        if (tid == 0) red[0] = t;
    }
    __syncthreads();
    float inv = 1.0f / red[0];
    #pragma unroll
    for (int i = 0; i < 2; i++) {
        int e0 = (tid + i * 256) * 4;
        if (e0 >= limit) continue;
        float* f = (float*)&v[i];
        #pragma unroll
        for (int j = 0; j < 4; j++) f[j] *= inv;
        *(float4*)(p + e0) = v[i];
    }
}

// 32x32 tiled transpose: out[c, r] = in[r, c], batched over z
__global__ void transpose_kernel(const float* __restrict__ in, float* __restrict__ out,
                                 int R, int Cc, long sIn, long sOut)
{
    __shared__ float t[32][33];
    const float* ip = in + blockIdx.z * sIn;
    float* op = out + blockIdx.z * sOut;
    const int c0 = blockIdx.x * 32, r0 = blockIdx.y * 32;
    for (int i = threadIdx.y; i < 32; i += 8)
        t[i][threadIdx.x] = ip[(long)(r0 + i) * Cc + c0 + threadIdx.x];
    __syncthreads();
    for (int i = threadIdx.y; i < 32; i += 8)
        op[(long)(c0 + i) * R + r0 + threadIdx.x] = t[threadIdx.x][i];
}

// ================= host side ====================================================
static float* sym_addr(const void* sym)
{
    void* p = nullptr;
    cudaGetSymbolAddress(&p, sym);
    return (float*)p;
}

static void run_gemm(const float* A, const float* B, float* C,
                     int M, int N, int K, int lda, int ldb, int ldc,
                     int Z, int zInner,
                     long sAo, long sAi, long sBo, long sBi, long sCo, long sCi,
                     int accumulate, int prec,
                     const int* offset_p = nullptr, int kclip = 0)
{
    dim3 grid(N / 128, M / 128, Z);
    if (prec == 3)
        gemm_cp<3,1><<<grid, 256, GEMM_SMEM>>>(A, B, C, K, lda, ldb, ldc,
                                               zInner, sAo, sAi, sBo, sBi, sCo, sCi,
                                               accumulate, offset_p, kclip);
    else
        gemm_cp<1,2><<<grid, 256, GEMM_SMEM>>>(A, B, C, K, lda, ldb, ldc,
                                               zInner, sAo, sAi, sBo, sBi, sCo, sCi,
                                               accumulate, offset_p, kclip);
}

extern "C" void kernel_launch(void* const* d_in, const int* in_sizes, int n_in,
                              void* d_out, int out_size)
{
    const float* x       = (const float*)d_in[0];
    const float* W_DKV   = (const float*)d_in[1];
    const float* W_KRope = (const float*)d_in[2];
    const float* W_Q     = (const float*)d_in[3];
    const float* W_UK    = (const float*)d_in[4];
    const float* W_UV    = (const float*)d_in[5];
    const float* W_O     = (const float*)d_in[6];
    const float* kvw     = (const float*)d_in[7];
    const int*   offset  = (const int*)d_in[8];
    float* out = (float*)d_out;

    static int s_init = 0;
    if (!s_init) {
        cudaFuncSetAttribute((const void*)gemm_cp<1,2>, cudaFuncAttributeMaxDynamicSharedMemorySize, GEMM_SMEM);
        cudaFuncSetAttribute((const void*)gemm_cp<3,1>, cudaFuncAttributeMaxDynamicSharedMemorySize, GEMM_SMEM);
        cudaFuncSetAttribute((const void*)gemm_proj3, cudaFuncAttributeMaxDynamicSharedMemorySize, GEMM_SMEM);
        cudaFuncSetAttribute((const void*)gemm_scores, cudaFuncAttributeMaxDynamicSharedMemorySize, GEMM_SMEM);
        s_init = 1;
    }

    float* ckv    = sym_addr(g_ckv);
    float* ckvT   = sym_addr(g_ckvT);
    float* krope  = sym_addr(g_krope);
    float* q      = sym_addr(g_q);
    float* qabs   = sym_addr(g_qabs);
    float* wukT   = sym_addr(g_wukT);
    float* scores = sym_addr(g_scores);
    float* ctxlat = sym_addr(g_ctxlat);
    float* ctx    = sym_addr(g_ctx);

    // 1-3) fused projections: ckv raw, krope raw, q   [tf32]
    {
        dim3 grid(36, 32, 1);
        gemm_proj3<<<grid, 256, GEMM_SMEM>>>(x, W_DKV, W_KRope, W_Q, ckv, krope, q);
    }
    rmsnorm_kernel<<<ROWS, 128>>>(ckv, kvw);
    {
        dim3 grid(LL / 32, SS / 32, BB), block(32, 8);
        transpose_kernel<<<grid, block>>>(ckv, ckvT, SS, LL,
                                          (long)SS * LL, (long)LL * SS);
    }
    {
        long total = (long)ROWS * HH * HALF_RD;
        rope_kernel<<<(int)((total + 255) / 256), 256>>>(krope, HH * RD, 0, offset);
        rope_kernel<<<(int)((total + 255) / 256), 256>>>(q, DOUT + HH * RD, DOUT, offset);
    }

    // W_UK^T per head
    {
        dim3 grid(LL / 32, HD / 32, HH), block(32, 8);
        transpose_kernel<<<grid, block>>>(W_UK, wukT, HD, LL,
                                          (long)HD * LL, (long)LL * HD);
    }

    // 4) q_abs  [tf32]
    run_gemm(q, wukT, qabs, ROWS, LL, HD,
             DOUT + HH * RD, HD, HH * LL,
             HH, HH,
             0, HD, 0, (long)LL * HD, 0, LL, 0, 1);

    // 5) fused scores = q_rope@k_rope^T + q_abs@c_kv^T  (causal block skip)
    {
        dim3 grid(TT / 128, SS / 128, BB * HH);
        gemm_scores<<<grid, 256, GEMM_SMEM>>>(q, krope, qabs, ckv, scores, offset);
    }

    // 6) masked scaled softmax (valid-only traffic)
    softmax_kernel<<<BB * HH * SS, 256>>>(scores, offset);

    // 7) ctx_lat = attn @ c_kv (via ckvT)  [tf32, K clipped causally]
    run_gemm(scores, ckvT, ctxlat, SS, LL, TT,
             TT, SS, HH * LL,
             BB * HH, HH,
             (long)HH * SS * TT, (long)SS * TT,
             (long)LL * SS, 0,
             (long)SS * HH * LL, LL, 0, 1, offset, 1);

    // 8) ctx = ctx_lat @ W_UV^T per head  [tf32x3]
    run_gemm(ctxlat, W_UV, ctx, ROWS, HD, LL,
             HH * LL, LL, DOUT,
             HH, HH,
             0, LL, 0, (long)HD * LL, 0, HD, 0, 3);

    // 9) out = ctx @ W_O^T  [tf32]
    run_gemm(ctx, W_O, out, ROWS, DIN, DOUT,
             DOUT, DOUT, DIN,
             1, 1, 0, 0, 0, 0, 0, 0, 0, 1);
}

// round 7
// speedup vs baseline: 5.8835x; 1.0893x over previous
#include <cuda_runtime.h>
#include <cuda_bf16.h>
#include <math.h>
#include <stdint.h>

// Problem constants
#define BB 2
#define SS 2048
#define TT 2048
#define DIN 2048
#define DOUT 2048
#define HH 16
#define RD 64
#define HALF_RD 32
#define LL 512
#define HD 128
#define ROWS (BB*SS)          // 4096

// ---------------- device scratch (static; no allocations) ---------------------
__device__ __align__(128) float g_ckv  [BB*SS*LL];
__device__ __align__(128) float g_ckvT [BB*LL*SS];
__device__ __align__(128) float g_krope[BB*SS*HH*RD];
__device__ __align__(128) float g_q    [BB*SS*(DOUT+HH*RD)];
__device__ __align__(128) float g_qabs [ROWS*HH*LL];
__device__ __align__(128) float g_wukT [DOUT*LL];
__device__ __align__(128) float g_scores[(long)BB*HH*SS*TT];
__device__ __align__(128) float g_ctxlat[ROWS*HH*LL];
__device__ __align__(128) float g_ctx  [ROWS*DOUT];
// tf32-rounded copies of harness inputs
__device__ __align__(128) float g_x32  [ROWS*DIN];
__device__ __align__(128) float g_wdkv32[LL*DIN];
__device__ __align__(128) float g_wkr32 [HH*RD*DIN];
__device__ __align__(128) float g_wq32  [(DOUT+HH*RD)*DIN];
__device__ __align__(128) float g_wo32  [DIN*DOUT];

// ================= helpers =====================================================
__device__ __forceinline__ float f2tf(float x) {
    uint32_t u; asm("cvt.rna.tf32.f32 %0, %1;" : "=r"(u) : "f"(x));
    return __uint_as_float(u);
}
__device__ __forceinline__ uint32_t smem_u32(const void* p) {
    uint32_t a;
    asm("{ .reg .u64 t; cvta.to.shared.u64 t, %1; cvt.u32.u64 %0, t; }" : "=r"(a) : "l"(p));
    return a;
}
__device__ __forceinline__ void cp16(uint32_t dst, const void* src) {
    asm volatile("cp.async.cg.shared.global [%0], [%1], 16;" :: "r"(dst), "l"(src));
}
#define CP_COMMIT() asm volatile("cp.async.commit_group;" ::: "memory")
#define CP_WAIT2()  asm volatile("cp.async.wait_group 2;"  ::: "memory")
#define CP_WAIT0()  asm volatile("cp.async.wait_group 0;"  ::: "memory")

__device__ __forceinline__ void ldsm4(uint32_t* r, uint32_t addr) {
    asm volatile("ldmatrix.sync.aligned.m8n8.x4.shared.b16 {%0,%1,%2,%3}, [%4];"
                 : "=r"(r[0]), "=r"(r[1]), "=r"(r[2]), "=r"(r[3]) : "r"(addr));
}

__device__ __forceinline__ void mma_tf32(float* c, const uint32_t* a, const uint32_t* b) {
    asm volatile(
        "mma.sync.aligned.m16n8k8.row.col.f32.tf32.tf32.f32 "
        "{%0,%1,%2,%3}, {%4,%5,%6,%7}, {%8,%9}, {%0,%1,%2,%3};"
        : "+f"(c[0]), "+f"(c[1]), "+f"(c[2]), "+f"(c[3])
        : "r"(a[0]), "r"(a[1]), "r"(a[2]), "r"(a[3]), "r"(b[0]), "r"(b[1]));
}

// ================= GEMM tile engine (cp.async + ldmatrix) ======================
// acc += A[0..128, :K] @ B[0..128, :K]^T ; caller pre-offsets A,B to tile origin.
// K % 16 == 0, K >= 64. CVT=0: operands already tf32-rounded (no cvt in loop).
#define STAGEF 5120                 // floats per stage (2560 A + 2560 B)
#define GEMM_SMEM (4*STAGEF*4)      // 81920 bytes

template<int PREC, int CVT>
__device__ __forceinline__ void gemm_tiles(
    const float* __restrict__ A, const float* __restrict__ B,
    int K, int lda, int ldb, float (*acc)[4][4], float* sm)
{
    const int tid  = threadIdx.x;
    const int lane = tid & 31;
    const int wid  = tid >> 5;
    const int wm   = wid >> 2;   // 0..1
    const int wn   = wid & 3;    // 0..3

    const uint32_t sbase = smem_u32(sm);

    const int r8   = lane & 7;
    const int aRow = wm * 64 + r8 + ((lane >> 3) & 1) * 8;
    const int aCol = ((lane >> 4) & 1) * 4;
    const uint32_t aOff = (uint32_t)(aRow * 20 + aCol) * 4;
    const int bRow = wn * 32 + r8 + ((lane >> 4) & 1) * 8;
    const int bCol = ((lane >> 3) & 1) * 4;
    const uint32_t bOff = (uint32_t)(bRow * 20 + bCol) * 4;

    const int crow = tid >> 2;          // 0..63
    const int cc4  = tid & 3;           // 0..3
    auto issue = [&](int c) {
        const int k0  = c << 4;
        const uint32_t st = sbase + (uint32_t)(c & 3) * (STAGEF * 4);
        #pragma unroll
        for (int i = 0; i < 2; i++) {
            int row = crow + i * 64;
            uint32_t d = st + (uint32_t)(row * 20 + cc4 * 4) * 4;
            cp16(d,             A + (long)row * lda + k0 + cc4 * 4);
            cp16(d + 2560 * 4,  B + (long)row * ldb + k0 + cc4 * 4);
        }
    };

    auto compute = [&](int c) {
        const uint32_t As = sbase + (uint32_t)(c & 3) * (STAGEF * 4);
        const uint32_t Bs = As + 2560 * 4;
        #pragma unroll
        for (int ks = 0; ks < 2; ks++) {
            uint32_t ah[4][4], bh[4][2];
            uint32_t al[4][4], bl[4][2];
            #pragma unroll
            for (int mt = 0; mt < 4; mt++) {
                uint32_t raw[4];
                ldsm4(raw, As + aOff + (uint32_t)(mt * 16 * 20 + ks * 8) * 4);
                #pragma unroll
                for (int i = 0; i < 4; i++) {
                    if (CVT) {
                        float v = __uint_as_float(raw[i]);
                        float h = f2tf(v);
                        ah[mt][i] = __float_as_uint(h);
                        if (PREC == 3) al[mt][i] = __float_as_uint(f2tf(v - h));
                    } else {
                        ah[mt][i] = raw[i];
                    }
                }
            }
            #pragma unroll
            for (int ntp = 0; ntp < 2; ntp++) {
                uint32_t raw[4];
                ldsm4(raw, Bs + bOff + (uint32_t)(ntp * 16 * 20 + ks * 8) * 4);
                #pragma unroll
                for (int i = 0; i < 4; i++) {
                    int nt = ntp * 2 + (i >> 1), kk = i & 1;
                    if (CVT) {
                        float v = __uint_as_float(raw[i]);
                        float h = f2tf(v);
                        bh[nt][kk] = __float_as_uint(h);
                        if (PREC == 3) bl[nt][kk] = __float_as_uint(f2tf(v - h));
                    } else {
                        bh[nt][kk] = raw[i];
                    }
                }
            }
            #pragma unroll
            for (int mt = 0; mt < 4; mt++)
                #pragma unroll
                for (int nt = 0; nt < 4; nt++)
                    mma_tf32(acc[mt][nt], ah[mt], bh[nt]);
            if (PREC == 3) {
                #pragma unroll
                for (int mt = 0; mt < 4; mt++)
                    #pragma unroll
                    for (int nt = 0; nt < 4; nt++) {
                        mma_tf32(acc[mt][nt], ah[mt], bl[nt]);
                        mma_tf32(acc[mt][nt], al[mt], bh[nt]);
                    }
            }
        }
    };

    const int NC = K >> 4;
    issue(0); CP_COMMIT();
    issue(1); CP_COMMIT();
    issue(2); CP_COMMIT();
    for (int c = 0; c < NC; c++) {
        CP_WAIT2();
        __syncthreads();
        if (c + 3 < NC) issue(c + 3);
        CP_COMMIT();
        compute(c);
    }
    CP_WAIT0();
    __syncthreads();
}

__device__ __forceinline__ void gemm_epilogue(
    float* __restrict__ C, int ldc, int m0, int n0,
    float (*acc)[4][4], int rnd)
{
    const int lane = threadIdx.x & 31;
    const int wid  = threadIdx.x >> 5;
    const int gid  = lane >> 2;
    const int tig  = lane & 3;
    const int wm   = wid >> 2;
    const int wn   = wid & 3;
    #pragma unroll
    for (int mt = 0; mt < 4; mt++) {
        #pragma unroll
        for (int nt = 0; nt < 4; nt++) {
            int r  = m0 + wm * 64 + mt * 16 + gid;
            int cc = n0 + wn * 32 + nt * 8 + tig * 2;
            float2 v0 = { acc[mt][nt][0], acc[mt][nt][1] };
            float2 v1 = { acc[mt][nt][2], acc[mt][nt][3] };
            if (rnd) {
                v0.x = f2tf(v0.x); v0.y = f2tf(v0.y);
                v1.x = f2tf(v1.x); v1.y = f2tf(v1.y);
            }
            *(float2*)&C[(long)r * ldc + cc]       = v0;
            *(float2*)&C[(long)(r + 8) * ldc + cc] = v1;
        }
    }
}

// generic batched GEMM; kclip=1 limits K to round128(m0+128+*offset_p) (causal)
template<int PREC, int CVT, int MINCTA>
__global__ void __launch_bounds__(256, MINCTA)
gemm_cp(const float* __restrict__ Ab, const float* __restrict__ Bb, float* __restrict__ Cb,
        int K, int lda, int ldb, int ldc,
        int zInner, long sAo, long sAi, long sBo, long sBi, long sCo, long sCi,
        int rnd, const int* offset_p, int kclip)
{
    extern __shared__ float sm[];
    const int z  = blockIdx.z;
    const int zo = z / zInner, zi = z % zInner;
    const int m0 = blockIdx.y * 128;
    const int n0 = blockIdx.x * 128;
    if (kclip) {
        int lim = m0 + 128 + *offset_p;
        lim = (lim + 127) & ~127;
        if (lim < K) K = lim;
    }
    float acc[4][4][4];
    #pragma unroll
    for (int mt = 0; mt < 4; mt++)
        #pragma unroll
        for (int nt = 0; nt < 4; nt++)
            #pragma unroll
            for (int i = 0; i < 4; i++) acc[mt][nt][i] = 0.0f;
    gemm_tiles<PREC, CVT>(Ab + zo * sAo + zi * sAi + (long)m0 * lda,
                          Bb + zo * sBo + zi * sBi + (long)n0 * ldb,
                          K, lda, ldb, acc, sm);
    gemm_epilogue(Cb + zo * sCo + zi * sCi, ldc, m0, n0, acc, rnd);
}

// fused triple projection: seg by blockIdx.x (4 | 8 | 24 blocks along N)
// inputs pre-rounded; outputs rounded to tf32
__global__ void __launch_bounds__(256, 2)
gemm_proj3(const float* __restrict__ x,
           const float* __restrict__ Wdkv, const float* __restrict__ Wkr,
           const float* __restrict__ Wq,
           float* __restrict__ ckv, float* __restrict__ krope, float* __restrict__ q)
{
    extern __shared__ float sm[];
    const int bx = blockIdx.x;
    const float* B; float* C; int ldc, n0;
    if (bx < 4)       { B = Wdkv; C = ckv;   ldc = LL;             n0 = bx * 128; }
    else if (bx < 12) { B = Wkr;  C = krope; ldc = HH * RD;        n0 = (bx - 4) * 128; }
    else              { B = Wq;   C = q;     ldc = DOUT + HH * RD; n0 = (bx - 12) * 128; }
    const int m0 = blockIdx.y * 128;
    float acc[4][4][4];
    #pragma unroll
    for (int mt = 0; mt < 4; mt++)
        #pragma unroll
        for (int nt = 0; nt < 4; nt++)
            #pragma unroll
            for (int i = 0; i < 4; i++) acc[mt][nt][i] = 0.0f;
    gemm_tiles<1, 0>(x + (long)m0 * DIN, B + (long)n0 * DIN, DIN, DIN, DIN, acc, sm);
    gemm_epilogue(C, ldc, m0, n0, acc, 1);
}

// fused scores: rope part (K=64) + latent part (K=512), causal block skip
__global__ void __launch_bounds__(256, 2)
gemm_scores(const float* __restrict__ q, const float* __restrict__ krope,
            const float* __restrict__ qabs, const float* __restrict__ ckv,
            float* __restrict__ scores, const int* __restrict__ offset_p)
{
    extern __shared__ float sm[];
    const int m0 = blockIdx.y * 128;
    const int n0 = blockIdx.x * 128;
    if (n0 > m0 + 127 + *offset_p) return;      // fully masked, never read
    const int b = blockIdx.z >> 4;
    const int h = blockIdx.z & 15;

    float acc[4][4][4];
    #pragma unroll
    for (int mt = 0; mt < 4; mt++)
        #pragma unroll
        for (int nt = 0; nt < 4; nt++)
            #pragma unroll
            for (int i = 0; i < 4; i++) acc[mt][nt][i] = 0.0f;

    const float* A1 = q + (long)b * SS * (DOUT + HH * RD) + DOUT + h * RD
                        + (long)m0 * (DOUT + HH * RD);
    const float* B1 = krope + (long)b * SS * (HH * RD) + h * RD + (long)n0 * (HH * RD);
    gemm_tiles<1, 0>(A1, B1, RD, DOUT + HH * RD, HH * RD, acc, sm);

    const float* A2 = qabs + (long)b * SS * (HH * LL) + h * LL + (long)m0 * (HH * LL);
    const float* B2 = ckv + (long)b * SS * LL + (long)n0 * LL;
    gemm_tiles<1, 0>(A2, B2, LL, HH * LL, LL, acc, sm);

    gemm_epilogue(scores + (long)blockIdx.z * SS * TT, TT, m0, n0, acc, 0);
}

// ================= small kernels ===============================================
// tf32-round a float array (float4 grid-stride)
__global__ void tf32ify_kernel(const float* __restrict__ in, float* __restrict__ out, int n4)
{
    int i = blockIdx.x * blockDim.x + threadIdx.x;
    if (i >= n4) return;
    float4 v = ((const float4*)in)[i];
    v.x = f2tf(v.x); v.y = f2tf(v.y); v.z = f2tf(v.z); v.w = f2tf(v.w);
    ((float4*)out)[i] = v;
}

__global__ void rmsnorm_kernel(float* __restrict__ data, const float* __restrict__ w)
{
    const int row = blockIdx.x;
    float* p = data + (long)row * LL;
    float ss = 0.0f;
    for (int i = threadIdx.x; i < LL; i += blockDim.x) { float v = p[i]; ss += v * v; }
    __shared__ float red[32];
    for (int o = 16; o; o >>= 1) ss += __shfl_xor_sync(0xffffffffu, ss, o);
    if ((threadIdx.x & 31) == 0) red[threadIdx.x >> 5] = ss;
    __syncthreads();
    if (threadIdx.x < 32) {
        float v = (threadIdx.x < (blockDim.x >> 5)) ? red[threadIdx.x] : 0.0f;
        for (int o = 16; o; o >>= 1) v += __shfl_xor_sync(0xffffffffu, v, o);
        if (threadIdx.x == 0) red[0] = v;
    }
    __syncthreads();
    float rstd = rsqrtf(red[0] / (float)LL + 1e-6f);
    for (int i = threadIdx.x; i < LL; i += blockDim.x)
        p[i] = f2tf(p[i] * rstd * w[i]);
}

__global__ void rope_kernel(float* __restrict__ data, int ld, int colbase,
                            const int* __restrict__ offset_p)
{
    long idx = (long)blockIdx.x * blockDim.x + threadIdx.x;
    const long total = (long)ROWS * HH * HALF_RD;
    if (idx >= total) return;
    int  j   = (int)(idx % HALF_RD);
    int  h   = (int)((idx / HALF_RD) % HH);
    long row = idx / (HALF_RD * HH);
    int  s   = (int)(row % SS);
    float pos = (float)(s + *offset_p);
    float inv = expf(-(float)j * (logf(10000.0f) / 32.0f));
    float ang = pos * inv;
    float c  = cosf(ang);
    float si = sinf(ang);
    float* p = data + row * (long)ld + colbase + h * RD;
    float x1 = p[j], x2 = p[j + HALF_RD];
    p[j]           = f2tf(x1 * c - x2 * si);
    p[j + HALF_RD] = f2tf(x2 * c + x1 * si);
}

// masked scaled softmax; loads only valid part, writes tf32-rounded probs
__global__ void __launch_bounds__(256)
softmax_kernel(float* __restrict__ scores, const int* __restrict__ offset_p)
{
    const long row = blockIdx.x;            // (b*H+h)*S + s
    const int  s   = (int)(row % SS);
    const int  off = *offset_p;
    int valid = s + off + 1;
    if (valid > TT) valid = TT;
    int limit = ((s & ~127) + 128 + off + 127) & ~127;
    if (limit > TT) limit = TT;
    float* p = scores + row * (long)TT;
    const float scale = rsqrtf((float)(HD + RD));
    const int tid = threadIdx.x;

    float4 v[2];
    float m = -INFINITY;
    #pragma unroll
    for (int i = 0; i < 2; i++) {
        int e0 = (tid + i * 256) * 4;
        float* f = (float*)&v[i];
        if (e0 < valid) {
            v[i] = *(const float4*)(p + e0);
            #pragma unroll
            for (int j = 0; j < 4; j++) {
                f[j] = (e0 + j < valid) ? f[j] * scale : -INFINITY;
                m = fmaxf(m, f[j]);
            }
        } else {
            f[0] = f[1] = f[2] = f[3] = -INFINITY;
        }
    }
    __shared__ float red[32];
    for (int o = 16; o; o >>= 1) m = fmaxf(m, __shfl_xor_sync(0xffffffffu, m, o));
    if ((tid & 31) == 0) red[tid >> 5] = m;
    __syncthreads();
    if (tid < 32) {
        float t = (tid < 8) ? red[tid] : -INFINITY;
        for (int o = 16; o; o >>= 1) t = fmaxf(t, __shfl_xor_sync(0xffffffffu, t, o));
        if (tid == 0) red[0] = t;
    }
    __syncthreads();
    m = red[0];
    __syncthreads();

    float sum = 0.0f;
    #pragma unroll
    for (int i = 0; i < 2; i++) {
        float* f = (float*)&v[i];
        #pragma unroll
        for (int j = 0; j < 4; j++) {
            float e = (f[j] == -INFINITY) ? 0.0f : expf(f[j] - m);
            f[j] = e;
            sum += e;
        }
    }
    for (int o = 16; o; o >>= 1) sum += __shfl_xor_sync(0xffffffffu, sum, o);
    if ((tid & 31) == 0) red[tid >> 5] = sum;
    __syncthreads();
    if (tid < 32) {
        float t = (tid < 8) ? red[tid] : 0.0f;
        for (int o = 16; o; o >>= 1) t += __shfl_xor_sync(0xffffffffu, t, o);
        if (tid == 0) red[0] = t;
    }
    __syncthreads();
    float inv = 1.0f / red[0];
    #pragma unroll
    for (int i = 0; i < 2; i++) {
        int e0 = (tid + i * 256) * 4;
        if (e0 >= limit) continue;
        float* f = (float*)&v[i];
        #pragma unroll
        for (int j = 0; j < 4; j++) f[j] = f2tf(f[j] * inv);
        *(float4*)(p + e0) = v[i];
    }
}

// 32x32 tiled transpose: out[c, r] = in[r, c], batched over z; rnd=1 rounds
__global__ void transpose_kernel(const float* __restrict__ in, float* __restrict__ out,
                                 int R, int Cc, long sIn, long sOut, int rnd)
{
    __shared__ float t[32][33];
    const float* ip = in + blockIdx.z * sIn;
    float* op = out + blockIdx.z * sOut;
    const int c0 = blockIdx.x * 32, r0 = blockIdx.y * 32;
    for (int i = threadIdx.y; i < 32; i += 8) {
        float v = ip[(long)(r0 + i) * Cc + c0 + threadIdx.x];
        t[i][threadIdx.x] = rnd ? f2tf(v) : v;
    }
    __syncthreads();
    for (int i = threadIdx.y; i < 32; i += 8)
        op[(long)(c0 + i) * R + r0 + threadIdx.x] = t[threadIdx.x][i];
}

// ================= host side ====================================================
static float* sym_addr(const void* sym)
{
    void* p = nullptr;
    cudaGetSymbolAddress(&p, sym);
    return (float*)p;
}

static void run_gemm(const float* A, const float* B, float* C,
                     int M, int N, int K, int lda, int ldb, int ldc,
                     int Z, int zInner,
                     long sAo, long sAi, long sBo, long sBi, long sCo, long sCi,
                     int rnd, int prec,
                     const int* offset_p = nullptr, int kclip = 0)
{
    dim3 grid(N / 128, M / 128, Z);
    if (prec == 3)
        gemm_cp<3,1,1><<<grid, 256, GEMM_SMEM>>>(A, B, C, K, lda, ldb, ldc,
                                                 zInner, sAo, sAi, sBo, sBi, sCo, sCi,
                                                 rnd, offset_p, kclip);
    else
        gemm_cp<1,0,2><<<grid, 256, GEMM_SMEM>>>(A, B, C, K, lda, ldb, ldc,
                                                 zInner, sAo, sAi, sBo, sBi, sCo, sCi,
                                                 rnd, offset_p, kclip);
}

extern "C" void kernel_launch(void* const* d_in, const int* in_sizes, int n_in,
                              void* d_out, int out_size)
{
    const float* x       = (const float*)d_in[0];
    const float* W_DKV   = (const float*)d_in[1];
    const float* W_KRope = (const float*)d_in[2];
    const float* W_Q     = (const float*)d_in[3];
    const float* W_UK    = (const float*)d_in[4];
    const float* W_UV    = (const float*)d_in[5];
    const float* W_O     = (const float*)d_in[6];
    const float* kvw     = (const float*)d_in[7];
    const int*   offset  = (const int*)d_in[8];
    float* out = (float*)d_out;

    static int s_init = 0;
    if (!s_init) {
        cudaFuncSetAttribute((const void*)gemm_cp<1,0,2>, cudaFuncAttributeMaxDynamicSharedMemorySize, GEMM_SMEM);
        cudaFuncSetAttribute((const void*)gemm_cp<3,1,1>, cudaFuncAttributeMaxDynamicSharedMemorySize, GEMM_SMEM);
        cudaFuncSetAttribute((const void*)gemm_proj3, cudaFuncAttributeMaxDynamicSharedMemorySize, GEMM_SMEM);
        cudaFuncSetAttribute((const void*)gemm_scores, cudaFuncAttributeMaxDynamicSharedMemorySize, GEMM_SMEM);
        s_init = 1;
    }

    float* ckv    = sym_addr(g_ckv);
    float* ckvT   = sym_addr(g_ckvT);
    float* krope  = sym_addr(g_krope);
    float* q      = sym_addr(g_q);
    float* qabs   = sym_addr(g_qabs);
    float* wukT   = sym_addr(g_wukT);
    float* scores = sym_addr(g_scores);
    float* ctxlat = sym_addr(g_ctxlat);
    float* ctx    = sym_addr(g_ctx);
    float* x32    = sym_addr(g_x32);
    float* wdkv32 = sym_addr(g_wdkv32);
    float* wkr32  = sym_addr(g_wkr32);
    float* wq32   = sym_addr(g_wq32);
    float* wo32   = sym_addr(g_wo32);

    // 0) tf32-round the raw inputs used by no-cvt GEMMs
    tf32ify_kernel<<<(ROWS*DIN/4 + 255)/256, 256>>>(x, x32, ROWS*DIN/4);
    tf32ify_kernel<<<(LL*DIN/4 + 255)/256, 256>>>(W_DKV, wdkv32, LL*DIN/4);
    tf32ify_kernel<<<(HH*RD*DIN/4 + 255)/256, 256>>>(W_KRope, wkr32, HH*RD*DIN/4);
    tf32ify_kernel<<<((DOUT+HH*RD)*DIN/4 + 255)/256, 256>>>(W_Q, wq32, (DOUT+HH*RD)*DIN/4);
    tf32ify_kernel<<<(DIN*DOUT/4 + 255)/256, 256>>>(W_O, wo32, DIN*DOUT/4);

    // 1-3) fused projections: ckv raw, krope raw, q   [no-cvt, rounded out]
    {
        dim3 grid(36, 32, 1);
        gemm_proj3<<<grid, 256, GEMM_SMEM>>>(x32, wdkv32, wkr32, wq32, ckv, krope, q);
    }
    rmsnorm_kernel<<<ROWS, 128>>>(ckv, kvw);
    {
        dim3 grid(LL / 32, SS / 32, BB), block(32, 8);
        transpose_kernel<<<grid, block>>>(ckv, ckvT, SS, LL,
                                          (long)SS * LL, (long)LL * SS, 0);
    }
    {
        long total = (long)ROWS * HH * HALF_RD;
        rope_kernel<<<(int)((total + 255) / 256), 256>>>(krope, HH * RD, 0, offset);
        rope_kernel<<<(int)((total + 255) / 256), 256>>>(q, DOUT + HH * RD, DOUT, offset);
    }

    // W_UK^T per head (rounded during transpose)
    {
        dim3 grid(LL / 32, HD / 32, HH), block(32, 8);
        transpose_kernel<<<grid, block>>>(W_UK, wukT, HD, LL,
                                          (long)HD * LL, (long)LL * HD, 1);
    }

    // 4) q_abs  [no-cvt, rounded out]
    run_gemm(q, wukT, qabs, ROWS, LL, HD,
             DOUT + HH * RD, HD, HH * LL,
             HH, HH,
             0, HD, 0, (long)LL * HD, 0, LL, 1, 1);

    // 5) fused scores (causal block skip) [no-cvt]
    {
        dim3 grid(TT / 128, SS / 128, BB * HH);
        gemm_scores<<<grid, 256, GEMM_SMEM>>>(q, krope, qabs, ckv, scores, offset);
    }

    // 6) masked scaled softmax (writes tf32-rounded probs)
    softmax_kernel<<<BB * HH * SS, 256>>>(scores, offset);

    // 7) ctx_lat = attn @ c_kv (via ckvT)  [no-cvt, K clipped causally, fp32 out]
    run_gemm(scores, ckvT, ctxlat, SS, LL, TT,
             TT, SS, HH * LL,
             BB * HH, HH,
             (long)HH * SS * TT, (long)SS * TT,
             (long)LL * SS, 0,
             (long)SS * HH * LL, LL, 0, 1, offset, 1);

    // 8) ctx = ctx_lat @ W_UV^T per head  [tf32x3 w/ cvt, rounded out]
    run_gemm(ctxlat, W_UV, ctx, ROWS, HD, LL,
             HH * LL, LL, DOUT,
             HH, HH,
             0, LL, 0, (long)HD * LL, 0, HD, 1, 3);

    // 9) out = ctx @ W_O^T  [no-cvt]
    run_gemm(ctx, wo32, out, ROWS, DIN, DOUT,
             DOUT, DOUT, DIN,
             1, 1, 0, 0, 0, 0, 0, 0, 0, 1);
}

// round 8
// speedup vs baseline: 9.3508x; 1.5893x over previous
#include <cuda_runtime.h>
#include <cuda_fp16.h>
#include <math.h>
#include <stdint.h>

// Problem constants
#define BB 2
#define SS 2048
#define TT 2048
#define DIN 2048
#define DOUT 2048
#define HH 16
#define RD 64
#define HALF_RD 32
#define LL 512
#define HD 128
#define ROWS (BB*SS)          // 4096
#define QW (DOUT+HH*RD)       // 3072

// ---------------- device scratch (static; no allocations) ---------------------
__device__ __align__(128) __half g_x16  [ROWS*DIN];
__device__ __align__(128) __half g_wdkv16[LL*DIN];
__device__ __align__(128) __half g_wkr16 [HH*RD*DIN];
__device__ __align__(128) __half g_wq16  [QW*DIN];
__device__ __align__(128) __half g_wo16  [DIN*DOUT];
__device__ __align__(128) __half g_ckv16 [BB*SS*LL];
__device__ __align__(128) __half g_ckvT16[BB*LL*SS];
__device__ __align__(128) __half g_krope16[BB*SS*HH*RD];
__device__ __align__(128) __half g_q16   [BB*SS*QW];
__device__ __align__(128) __half g_qabs16[ROWS*HH*LL];
__device__ __align__(128) __half g_wukT16[LL*DOUT];
__device__ __align__(128) float  g_scores[(long)BB*HH*SS*TT];
__device__ __align__(128) __half g_probs16[(long)BB*HH*SS*TT];
__device__ __align__(128) float  g_ctxlat[ROWS*HH*LL];
__device__ __align__(128) __half g_ctx16 [ROWS*DOUT];

// ================= helpers =====================================================
__device__ __forceinline__ float f2tf(float x) {
    uint32_t u; asm("cvt.rna.tf32.f32 %0, %1;" : "=r"(u) : "f"(x));
    return __uint_as_float(u);
}
__device__ __forceinline__ uint32_t smem_u32(const void* p) {
    uint32_t a;
    asm("{ .reg .u64 t; cvta.to.shared.u64 t, %1; cvt.u32.u64 %0, t; }" : "=r"(a) : "l"(p));
    return a;
}
__device__ __forceinline__ void cp16(uint32_t dst, const void* src) {
    asm volatile("cp.async.cg.shared.global [%0], [%1], 16;" :: "r"(dst), "l"(src));
}
#define CP_COMMIT() asm volatile("cp.async.commit_group;" ::: "memory")
#define CP_WAIT2()  asm volatile("cp.async.wait_group 2;"  ::: "memory")
#define CP_WAIT0()  asm volatile("cp.async.wait_group 0;"  ::: "memory")

__device__ __forceinline__ void ldsm4(uint32_t* r, uint32_t addr) {
    asm volatile("ldmatrix.sync.aligned.m8n8.x4.shared.b16 {%0,%1,%2,%3}, [%4];"
                 : "=r"(r[0]), "=r"(r[1]), "=r"(r[2]), "=r"(r[3]) : "r"(addr));
}
__device__ __forceinline__ void mma_tf32(float* c, const uint32_t* a, const uint32_t* b) {
    asm volatile(
        "mma.sync.aligned.m16n8k8.row.col.f32.tf32.tf32.f32 "
        "{%0,%1,%2,%3}, {%4,%5,%6,%7}, {%8,%9}, {%0,%1,%2,%3};"
        : "+f"(c[0]), "+f"(c[1]), "+f"(c[2]), "+f"(c[3])
        : "r"(a[0]), "r"(a[1]), "r"(a[2]), "r"(a[3]), "r"(b[0]), "r"(b[1]));
}
__device__ __forceinline__ void mma_f16(float* c, const uint32_t* a, const uint32_t* b) {
    asm volatile(
        "mma.sync.aligned.m16n8k16.row.col.f32.f16.f16.f32 "
        "{%0,%1,%2,%3}, {%4,%5,%6,%7}, {%8,%9}, {%0,%1,%2,%3};"
        : "+f"(c[0]), "+f"(c[1]), "+f"(c[2]), "+f"(c[3])
        : "r"(a[0]), "r"(a[1]), "r"(a[2]), "r"(a[3]), "r"(b[0]), "r"(b[1]));
}

#define GEMM_SMEM 81920

// ================= FP16 GEMM tile engine (K-chunk 32) ==========================
// acc += A[0..128,:K] @ B[0..128,:K]^T ; half operands, fp32 accum.
// pitch 40 halves (80B) per row; stage = A(5120h)+B(5120h) = 20480 B.
__device__ __forceinline__ void gemm_tiles_h(
    const __half* __restrict__ A, const __half* __restrict__ B,
    int K, int lda, int ldb, float (*acc)[4][4], char* sm)
{
    const int tid  = threadIdx.x;
    const int lane = tid & 31;
    const int wid  = tid >> 5;
    const int wm   = wid >> 2;
    const int wn   = wid & 3;

    const uint32_t sbase = smem_u32(sm);

    const int aRow = wm * 64 + (lane & 7) + ((lane >> 3) & 1) * 8;
    const uint32_t aOff = (uint32_t)(aRow * 40 + ((lane >> 4) & 1) * 8) * 2;
    const int bRow = wn * 32 + (lane & 7) + ((lane >> 4) & 1) * 8;
    const uint32_t bOff = (uint32_t)(bRow * 40 + ((lane >> 3) & 1) * 8) * 2;

    const int crow = tid >> 2;          // 0..63
    const int cc   = (tid & 3) * 8;     // half offset 0,8,16,24
    auto issue = [&](int c) {
        const int k0 = c << 5;
        const uint32_t st = sbase + (uint32_t)(c & 3) * 20480;
        #pragma unroll
        for (int i = 0; i < 2; i++) {
            int row = crow + i * 64;
            uint32_t d = st + (uint32_t)(row * 40 + cc) * 2;
            cp16(d,             A + (long)row * lda + k0 + cc);
            cp16(d + 10240,     B + (long)row * ldb + k0 + cc);
        }
    };

    auto compute = [&](int c) {
        const uint32_t As = sbase + (uint32_t)(c & 3) * 20480;
        const uint32_t Bs = As + 10240;
        #pragma unroll
        for (int ks = 0; ks < 2; ks++) {
            uint32_t ah[4][4], bh[4][2];
            #pragma unroll
            for (int mt = 0; mt < 4; mt++)
                ldsm4(ah[mt], As + aOff + (uint32_t)(mt * 16 * 40 + ks * 16) * 2);
            #pragma unroll
            for (int np = 0; np < 2; np++) {
                uint32_t raw[4];
                ldsm4(raw, Bs + bOff + (uint32_t)(np * 16 * 40 + ks * 16) * 2);
                bh[np * 2][0] = raw[0]; bh[np * 2][1] = raw[1];
                bh[np * 2 + 1][0] = raw[2]; bh[np * 2 + 1][1] = raw[3];
            }
            #pragma unroll
            for (int mt = 0; mt < 4; mt++)
                #pragma unroll
                for (int nt = 0; nt < 4; nt++)
                    mma_f16(acc[mt][nt], ah[mt], bh[nt]);
        }
    };

    const int NC = K >> 5;
    if (0 < NC) issue(0); CP_COMMIT();
    if (1 < NC) issue(1); CP_COMMIT();
    if (2 < NC) issue(2); CP_COMMIT();
    for (int c = 0; c < NC; c++) {
        CP_WAIT2();
        __syncthreads();
        if (c + 3 < NC) issue(c + 3);
        CP_COMMIT();
        compute(c);
    }
    CP_WAIT0();
    __syncthreads();
}

// epilogue: OUTH=1 writes __half, else float
template<int OUTH>
__device__ __forceinline__ void gemm_epi(
    void* __restrict__ Cv, int ldc, int m0, int n0, float (*acc)[4][4])
{
    const int lane = threadIdx.x & 31;
    const int wid  = threadIdx.x >> 5;
    const int gid  = lane >> 2;
    const int tig  = lane & 3;
    const int wm   = wid >> 2;
    const int wn   = wid & 3;
    #pragma unroll
    for (int mt = 0; mt < 4; mt++) {
        #pragma unroll
        for (int nt = 0; nt < 4; nt++) {
            int r  = m0 + wm * 64 + mt * 16 + gid;
            int cc = n0 + wn * 32 + nt * 8 + tig * 2;
            if (OUTH) {
                __half* C = (__half*)Cv;
                *(__half2*)&C[(long)r * ldc + cc] =
                    __floats2half2_rn(acc[mt][nt][0], acc[mt][nt][1]);
                *(__half2*)&C[(long)(r + 8) * ldc + cc] =
                    __floats2half2_rn(acc[mt][nt][2], acc[mt][nt][3]);
            } else {
                float* C = (float*)Cv;
                float2 v0 = { acc[mt][nt][0], acc[mt][nt][1] };
                float2 v1 = { acc[mt][nt][2], acc[mt][nt][3] };
                *(float2*)&C[(long)r * ldc + cc]       = v0;
                *(float2*)&C[(long)(r + 8) * ldc + cc] = v1;
            }
        }
    }
}

#define ACC_INIT(acc) { _Pragma("unroll") for (int _m = 0; _m < 4; _m++) \
    _Pragma("unroll") for (int _n = 0; _n < 4; _n++) \
    _Pragma("unroll") for (int _i = 0; _i < 4; _i++) acc[_m][_n][_i] = 0.0f; }

// generic batched fp16 GEMM; kclip limits K causally
template<int OUTH>
__global__ void __launch_bounds__(256, 2)
gemm_h(const __half* __restrict__ Ab, const __half* __restrict__ Bb, void* __restrict__ Cb,
       int K, int lda, int ldb, int ldc,
       int zInner, long sAo, long sAi, long sBo, long sBi, long sCo, long sCi,
       const int* offset_p, int kclip)
{
    extern __shared__ char smc[];
    const int z  = blockIdx.z;
    const int zo = z / zInner, zi = z % zInner;
    const int m0 = blockIdx.y * 128;
    const int n0 = blockIdx.x * 128;
    if (kclip) {
        int lim = m0 + 128 + *offset_p;
        lim = (lim + 127) & ~127;
        if (lim < K) K = lim;
    }
    float acc[4][4][4];
    ACC_INIT(acc);
    gemm_tiles_h(Ab + zo * sAo + zi * sAi + (long)m0 * lda,
                 Bb + zo * sBo + zi * sBi + (long)n0 * ldb,
                 K, lda, ldb, acc, smc);
    if (OUTH)
        gemm_epi<1>((__half*)Cb + zo * sCo + zi * sCi, ldc, m0, n0, acc);
    else
        gemm_epi<0>((float*)Cb + zo * sCo + zi * sCi, ldc, m0, n0, acc);
}

// fused triple projection (half out)
__global__ void __launch_bounds__(256, 2)
gemm_proj3(const __half* __restrict__ x,
           const __half* __restrict__ Wdkv, const __half* __restrict__ Wkr,
           const __half* __restrict__ Wq,
           __half* __restrict__ ckv, __half* __restrict__ krope, __half* __restrict__ q)
{
    extern __shared__ char smc[];
    const int bx = blockIdx.x;
    const __half* B; __half* C; int ldc, n0;
    if (bx < 4)       { B = Wdkv; C = ckv;   ldc = LL;       n0 = bx * 128; }
    else if (bx < 12) { B = Wkr;  C = krope; ldc = HH * RD;  n0 = (bx - 4) * 128; }
    else              { B = Wq;   C = q;     ldc = QW;       n0 = (bx - 12) * 128; }
    const int m0 = blockIdx.y * 128;
    float acc[4][4][4];
    ACC_INIT(acc);
    gemm_tiles_h(x + (long)m0 * DIN, B + (long)n0 * DIN, DIN, DIN, DIN, acc, smc);
    gemm_epi<1>(C, ldc, m0, n0, acc);
}

// fused scores: rope (K=64) + latent (K=512), causal block skip, fp32 out
__global__ void __launch_bounds__(256, 2)
gemm_scores(const __half* __restrict__ q, const __half* __restrict__ krope,
            const __half* __restrict__ qabs, const __half* __restrict__ ckv,
            float* __restrict__ scores, const int* __restrict__ offset_p)
{
    extern __shared__ char smc[];
    const int m0 = blockIdx.y * 128;
    const int n0 = blockIdx.x * 128;
    if (n0 > m0 + 127 + *offset_p) return;
    const int b = blockIdx.z >> 4;
    const int h = blockIdx.z & 15;

    float acc[4][4][4];
    ACC_INIT(acc);

    const __half* A1 = q + (long)b * SS * QW + DOUT + h * RD + (long)m0 * QW;
    const __half* B1 = krope + (long)b * SS * (HH * RD) + h * RD + (long)n0 * (HH * RD);
    gemm_tiles_h(A1, B1, RD, QW, HH * RD, acc, smc);

    const __half* A2 = qabs + (long)b * SS * (HH * LL) + h * LL + (long)m0 * (HH * LL);
    const __half* B2 = ckv + (long)b * SS * LL + (long)n0 * LL;
    gemm_tiles_h(A2, B2, LL, HH * LL, LL, acc, smc);

    gemm_epi<0>(scores + (long)blockIdx.z * SS * TT, TT, m0, n0, acc);
}

// ================= FP32/tf32x3 engine for the ctx GEMM (precision-critical) ====
__device__ __forceinline__ void gemm_tiles_f3(
    const float* __restrict__ A, const float* __restrict__ B,
    int K, int lda, int ldb, float (*acc)[4][4], float* sm)
{
    const int tid  = threadIdx.x;
    const int lane = tid & 31;
    const int wid  = tid >> 5;
    const int wm   = wid >> 2;
    const int wn   = wid & 3;
    const uint32_t sbase = smem_u32(sm);

    const int r8   = lane & 7;
    const int aRow = wm * 64 + r8 + ((lane >> 3) & 1) * 8;
    const uint32_t aOff = (uint32_t)(aRow * 20 + ((lane >> 4) & 1) * 4) * 4;
    const int bRow = wn * 32 + r8 + ((lane >> 4) & 1) * 8;
    const uint32_t bOff = (uint32_t)(bRow * 20 + ((lane >> 3) & 1) * 4) * 4;

    const int crow = tid >> 2;
    const int cc4  = tid & 3;
    auto issue = [&](int c) {
        const int k0  = c << 4;
        const uint32_t st = sbase + (uint32_t)(c & 3) * 20480;
        #pragma unroll
        for (int i = 0; i < 2; i++) {
            int row = crow + i * 64;
            uint32_t d = st + (uint32_t)(row * 20 + cc4 * 4) * 4;
            cp16(d,          A + (long)row * lda + k0 + cc4 * 4);
            cp16(d + 10240,  B + (long)row * ldb + k0 + cc4 * 4);
        }
    };
    auto compute = [&](int c) {
        const uint32_t As = sbase + (uint32_t)(c & 3) * 20480;
        const uint32_t Bs = As + 10240;
        #pragma unroll
        for (int ks = 0; ks < 2; ks++) {
            uint32_t ah[4][4], bh[4][2], al[4][4], bl[4][2];
            #pragma unroll
            for (int mt = 0; mt < 4; mt++) {
                uint32_t raw[4];
                ldsm4(raw, As + aOff + (uint32_t)(mt * 16 * 20 + ks * 8) * 4);
                #pragma unroll
                for (int i = 0; i < 4; i++) {
                    float v = __uint_as_float(raw[i]);
                    float h = f2tf(v);
                    ah[mt][i] = __float_as_uint(h);
                    al[mt][i] = __float_as_uint(f2tf(v - h));
                }
            }
            #pragma unroll
            for (int ntp = 0; ntp < 2; ntp++) {
                uint32_t raw[4];
                ldsm4(raw, Bs + bOff + (uint32_t)(ntp * 16 * 20 + ks * 8) * 4);
                #pragma unroll
                for (int i = 0; i < 4; i++) {
                    int nt = ntp * 2 + (i >> 1), kk = i & 1;
                    float v = __uint_as_float(raw[i]);
                    float h = f2tf(v);
                    bh[nt][kk] = __float_as_uint(h);
                    bl[nt][kk] = __float_as_uint(f2tf(v - h));
                }
            }
            #pragma unroll
            for (int mt = 0; mt < 4; mt++)
                #pragma unroll
                for (int nt = 0; nt < 4; nt++) {
                    mma_tf32(acc[mt][nt], ah[mt], bh[nt]);
                    mma_tf32(acc[mt][nt], ah[mt], bl[nt]);
                    mma_tf32(acc[mt][nt], al[mt], bh[nt]);
                }
        }
    };
    const int NC = K >> 4;
    issue(0); CP_COMMIT();
    issue(1); CP_COMMIT();
    issue(2); CP_COMMIT();
    for (int c = 0; c < NC; c++) {
        CP_WAIT2();
        __syncthreads();
        if (c + 3 < NC) issue(c + 3);
        CP_COMMIT();
        compute(c);
    }
    CP_WAIT0();
    __syncthreads();
}

// ctx = ctxlat @ W_UV^T per head, tf32x3, half output
__global__ void __launch_bounds__(256, 1)
gemm_ctx3(const float* __restrict__ ctxlat, const float* __restrict__ Wuv,
          __half* __restrict__ ctx)
{
    extern __shared__ float smf[];
    const int h  = blockIdx.z;
    const int m0 = blockIdx.y * 128;
    float acc[4][4][4];
    ACC_INIT(acc);
    gemm_tiles_f3(ctxlat + h * LL + (long)m0 * (HH * LL),
                  Wuv + (long)h * HD * LL,
                  LL, HH * LL, LL, acc, smf);
    gemm_epi<1>(ctx + h * HD, DOUT, m0, 0, acc);
}

// ================= small kernels ===============================================
__global__ void halfify_kernel(const float* __restrict__ in, __half* __restrict__ out, int n4)
{
    int i = blockIdx.x * blockDim.x + threadIdx.x;
    if (i >= n4) return;
    float4 v = ((const float4*)in)[i];
    __half2* o = (__half2*)out;
    o[i * 2]     = __floats2half2_rn(v.x, v.y);
    o[i * 2 + 1] = __floats2half2_rn(v.z, v.w);
}

__global__ void rmsnorm_kernel(__half* __restrict__ data, const float* __restrict__ w)
{
    const int row = blockIdx.x;
    __half* p = data + (long)row * LL;
    float ss = 0.0f;
    float vals[4];
    #pragma unroll
    for (int i = 0; i < 4; i++) {
        vals[i] = __half2float(p[threadIdx.x + i * 128]);
        ss += vals[i] * vals[i];
    }
    __shared__ float red[32];
    for (int o = 16; o; o >>= 1) ss += __shfl_xor_sync(0xffffffffu, ss, o);
    if ((threadIdx.x & 31) == 0) red[threadIdx.x >> 5] = ss;
    __syncthreads();
    if (threadIdx.x < 32) {
        float v = (threadIdx.x < 4) ? red[threadIdx.x] : 0.0f;
        for (int o = 16; o; o >>= 1) v += __shfl_xor_sync(0xffffffffu, v, o);
        if (threadIdx.x == 0) red[0] = v;
    }
    __syncthreads();
    float rstd = rsqrtf(red[0] / (float)LL + 1e-6f);
    #pragma unroll
    for (int i = 0; i < 4; i++)
        p[threadIdx.x + i * 128] = __float2half_rn(vals[i] * rstd * w[threadIdx.x + i * 128]);
}

__global__ void rope_kernel(__half* __restrict__ data, int ld, int colbase,
                            const int* __restrict__ offset_p)
{
    long idx = (long)blockIdx.x * blockDim.x + threadIdx.x;
    const long total = (long)ROWS * HH * HALF_RD;
    if (idx >= total) return;
    int  j   = (int)(idx % HALF_RD);
    int  h   = (int)((idx / HALF_RD) % HH);
    long row = idx / (HALF_RD * HH);
    int  s   = (int)(row % SS);
    float pos = (float)(s + *offset_p);
    float inv = expf(-(float)j * (logf(10000.0f) / 32.0f));
    float ang = pos * inv;
    float c  = cosf(ang);
    float si = sinf(ang);
    __half* p = data + row * (long)ld + colbase + h * RD;
    float x1 = __half2float(p[j]), x2 = __half2float(p[j + HALF_RD]);
    p[j]           = __float2half_rn(x1 * c - x2 * si);
    p[j + HALF_RD] = __float2half_rn(x2 * c + x1 * si);
}

// masked scaled softmax; fp32 scores in, half probs out (zero-filled to limit)
__global__ void __launch_bounds__(256)
softmax_kernel(const float* __restrict__ scores, __half* __restrict__ probs,
               const int* __restrict__ offset_p)
{
    const long row = blockIdx.x;            // (b*H+h)*S + s
    const int  s   = (int)(row % SS);
    const int  off = *offset_p;
    int valid = s + off + 1;
    if (valid > TT) valid = TT;
    int limit = ((s & ~127) + 128 + off + 127) & ~127;
    if (limit > TT) limit = TT;
    const float* p = scores + row * (long)TT;
    __half* op = probs + row * (long)TT;
    const float scale = rsqrtf((float)(HD + RD));
    const int tid = threadIdx.x;

    float4 v[2];
    float m = -INFINITY;
    #pragma unroll
    for (int i = 0; i < 2; i++) {
        int e0 = (tid + i * 256) * 4;
        float* f = (float*)&v[i];
        if (e0 < valid) {
            v[i] = *(const float4*)(p + e0);
            #pragma unroll
            for (int j = 0; j < 4; j++) {
                f[j] = (e0 + j < valid) ? f[j] * scale : -INFINITY;
                m = fmaxf(m, f[j]);
            }
        } else {
            f[0] = f[1] = f[2] = f[3] = -INFINITY;
        }
    }
    __shared__ float red[32];
    for (int o = 16; o; o >>= 1) m = fmaxf(m, __shfl_xor_sync(0xffffffffu, m, o));
    if ((tid & 31) == 0) red[tid >> 5] = m;
    __syncthreads();
    if (tid < 32) {
        float t = (tid < 8) ? red[tid] : -INFINITY;
        for (int o = 16; o; o >>= 1) t = fmaxf(t, __shfl_xor_sync(0xffffffffu, t, o));
        if (tid == 0) red[0] = t;
    }
    __syncthreads();
    m = red[0];
    __syncthreads();

    float sum = 0.0f;
    #pragma unroll
    for (int i = 0; i < 2; i++) {
        float* f = (float*)&v[i];
        #pragma unroll
        for (int j = 0; j < 4; j++) {
            float e = (f[j] == -INFINITY) ? 0.0f : expf(f[j] - m);
            f[j] = e;
            sum += e;
        }
    }
    for (int o = 16; o; o >>= 1) sum += __shfl_xor_sync(0xffffffffu, sum, o);
    if ((tid & 31) == 0) red[tid >> 5] = sum;
    __syncthreads();
    if (tid < 32) {
        float t = (tid < 8) ? red[tid] : 0.0f;
        for (int o = 16; o; o >>= 1) t += __shfl_xor_sync(0xffffffffu, t, o);
        if (tid == 0) red[0] = t;
    }
    __syncthreads();
    float inv = 1.0f / red[0];
    #pragma unroll
    for (int i = 0; i < 2; i++) {
        int e0 = (tid + i * 256) * 4;
        if (e0 >= limit) continue;
        float* f = (float*)&v[i];
        __half2 h0 = __floats2half2_rn(f[0] * inv, f[1] * inv);
        __half2 h1 = __floats2half2_rn(f[2] * inv, f[3] * inv);
        *(__half2*)(op + e0)     = h0;
        *(__half2*)(op + e0 + 2) = h1;
    }
}

// half->half 32x32 transpose, batched over z
__global__ void transpose_h(const __half* __restrict__ in, __half* __restrict__ out,
                            int R, int Cc, long sIn, long sOut)
{
    __shared__ __half t[32][33];
    const __half* ip = in + blockIdx.z * sIn;
    __half* op = out + blockIdx.z * sOut;
    const int c0 = blockIdx.x * 32, r0 = blockIdx.y * 32;
    for (int i = threadIdx.y; i < 32; i += 8)
        t[i][threadIdx.x] = ip[(long)(r0 + i) * Cc + c0 + threadIdx.x];
    __syncthreads();
    for (int i = threadIdx.y; i < 32; i += 8)
        op[(long)(c0 + i) * R + r0 + threadIdx.x] = t[threadIdx.x][i];
}

// float->half 32x32 transpose, batched over z (for W_UK)
__global__ void transpose_f2h(const float* __restrict__ in, __half* __restrict__ out,
                              int R, int Cc, long sIn, long sOut)
{
    __shared__ __half t[32][33];
    const float* ip = in + blockIdx.z * sIn;
    __half* op = out + blockIdx.z * sOut;
    const int c0 = blockIdx.x * 32, r0 = blockIdx.y * 32;
    for (int i = threadIdx.y; i < 32; i += 8)
        t[i][threadIdx.x] = __float2half_rn(ip[(long)(r0 + i) * Cc + c0 + threadIdx.x]);
    __syncthreads();
    for (int i = threadIdx.y; i < 32; i += 8)
        op[(long)(c0 + i) * R + r0 + threadIdx.x] = t[threadIdx.x][i];
}

// ================= host side ====================================================
template<typename T>
static T* sym_addr(const void* sym)
{
    void* p = nullptr;
    cudaGetSymbolAddress(&p, sym);
    return (T*)p;
}

extern "C" void kernel_launch(void* const* d_in, const int* in_sizes, int n_in,
                              void* d_out, int out_size)
{
    const float* x       = (const float*)d_in[0];
    const float* W_DKV   = (const float*)d_in[1];
    const float* W_KRope = (const float*)d_in[2];
    const float* W_Q     = (const float*)d_in[3];
    const float* W_UK    = (const float*)d_in[4];
    const float* W_UV    = (const float*)d_in[5];
    const float* W_O     = (const float*)d_in[6];
    const float* kvw     = (const float*)d_in[7];
    const int*   offset  = (const int*)d_in[8];
    float* out = (float*)d_out;

    static int s_init = 0;
    if (!s_init) {
        cudaFuncSetAttribute((const void*)gemm_h<0>, cudaFuncAttributeMaxDynamicSharedMemorySize, GEMM_SMEM);
        cudaFuncSetAttribute((const void*)gemm_h<1>, cudaFuncAttributeMaxDynamicSharedMemorySize, GEMM_SMEM);
        cudaFuncSetAttribute((const void*)gemm_proj3, cudaFuncAttributeMaxDynamicSharedMemorySize, GEMM_SMEM);
        cudaFuncSetAttribute((const void*)gemm_scores, cudaFuncAttributeMaxDynamicSharedMemorySize, GEMM_SMEM);
        cudaFuncSetAttribute((const void*)gemm_ctx3, cudaFuncAttributeMaxDynamicSharedMemorySize, GEMM_SMEM);
        s_init = 1;
    }

    __half* x16    = sym_addr<__half>(g_x16);
    __half* wdkv16 = sym_addr<__half>(g_wdkv16);
    __half* wkr16  = sym_addr<__half>(g_wkr16);
    __half* wq16   = sym_addr<__half>(g_wq16);
    __half* wo16   = sym_addr<__half>(g_wo16);
    __half* ckv16  = sym_addr<__half>(g_ckv16);
    __half* ckvT16 = sym_addr<__half>(g_ckvT16);
    __half* krope16= sym_addr<__half>(g_krope16);
    __half* q16    = sym_addr<__half>(g_q16);
    __half* qabs16 = sym_addr<__half>(g_qabs16);
    __half* wukT16 = sym_addr<__half>(g_wukT16);
    float*  scores = sym_addr<float>(g_scores);
    __half* probs16= sym_addr<__half>(g_probs16);
    float*  ctxlat = sym_addr<float>(g_ctxlat);
    __half* ctx16  = sym_addr<__half>(g_ctx16);

    // 0) half-round inputs
    halfify_kernel<<<(ROWS*DIN/4 + 255)/256, 256>>>(x, x16, ROWS*DIN/4);
    halfify_kernel<<<(LL*DIN/4 + 255)/256, 256>>>(W_DKV, wdkv16, LL*DIN/4);
    halfify_kernel<<<(HH*RD*DIN/4 + 255)/256, 256>>>(W_KRope, wkr16, HH*RD*DIN/4);
    halfify_kernel<<<(QW*DIN/4 + 255)/256, 256>>>(W_Q, wq16, QW*DIN/4);
    halfify_kernel<<<(DIN*DOUT/4 + 255)/256, 256>>>(W_O, wo16, DIN*DOUT/4);

    // 1-3) fused projections
    {
        dim3 grid(36, 32, 1);
        gemm_proj3<<<grid, 256, GEMM_SMEM>>>(x16, wdkv16, wkr16, wq16,
                                             ckv16, krope16, q16);
    }
    rmsnorm_kernel<<<ROWS, 128>>>(ckv16, kvw);
    {
        dim3 grid(LL / 32, SS / 32, BB), block(32, 8);
        transpose_h<<<grid, block>>>(ckv16, ckvT16, SS, LL,
                                     (long)SS * LL, (long)LL * SS);
    }
    {
        long total = (long)ROWS * HH * HALF_RD;
        rope_kernel<<<(int)((total + 255) / 256), 256>>>(krope16, HH * RD, 0, offset);
        rope_kernel<<<(int)((total + 255) / 256), 256>>>(q16, QW, DOUT, offset);
    }

    // W_UK^T per head (fp32 -> half)
    {
        dim3 grid(LL / 32, HD / 32, HH), block(32, 8);
        transpose_f2h<<<grid, block>>>(W_UK, wukT16, HD, LL,
                                       (long)HD * LL, (long)LL * HD);
    }

    // 4) q_abs (half out)
    {
        dim3 grid(LL / 128, ROWS / 128, HH);
        gemm_h<1><<<grid, 256, GEMM_SMEM>>>(q16, wukT16, qabs16,
            HD, QW, HD, HH * LL,
            HH, 0, HD, 0, (long)LL * HD, 0, LL, nullptr, 0);
    }

    // 5) fused scores (causal block skip)
    {
        dim3 grid(TT / 128, SS / 128, BB * HH);
        gemm_scores<<<grid, 256, GEMM_SMEM>>>(q16, krope16, qabs16, ckv16,
                                              scores, offset);
    }

    // 6) softmax -> half probs
    softmax_kernel<<<BB * HH * SS, 256>>>(scores, probs16, offset);

    // 7) ctx_lat = probs @ ckvT (K clipped causally), fp32 out
    {
        dim3 grid(LL / 128, SS / 128, BB * HH);
        gemm_h<0><<<grid, 256, GEMM_SMEM>>>(probs16, ckvT16, ctxlat,
            TT, TT, SS, HH * LL,
            HH, (long)HH * SS * TT, (long)SS * TT,
            (long)LL * SS, 0,
            (long)SS * HH * LL, LL, offset, 1);
    }

    // 8) ctx = ctxlat @ W_UV^T per head (tf32x3, half out)
    {
        dim3 grid(1, ROWS / 128, HH);
        gemm_ctx3<<<grid, 256, GEMM_SMEM>>>(ctxlat, W_UV, ctx16);
    }

    // 9) out = ctx @ W_O^T (fp32 out)
    {
        dim3 grid(DIN / 128, ROWS / 128, 1);
        gemm_h<0><<<grid, 256, GEMM_SMEM>>>(ctx16, wo16, out,
            DOUT, DOUT, DOUT, DIN,
            1, 0, 0, 0, 0, 0, 0, nullptr, 0);
    }
}